// round 1
// baseline (speedup 1.0000x reference)
#include <cuda_runtime.h>
#include <math.h>

#define NLAT 721
#define NLON 1440
#define NB   4
#define KOFF 2
#define DT   0.01f

#define FOFF   ((size_t)NB * NLAT * NLON)      // one field worth of elements
#define RSTRIDE 2884                            // padded duplicated row (need 2881)
#define NROWS  15                               // 3 fields x 5 lat offsets
#define BLOCK  384
#define NCOMP  360                              // computing threads (4 lons each)
#define SMEM_BYTES (NROWS * RSTRIDE * 4)

static const double DTH    = 3.14159265358979323846 / (NLAT - 1);
#define D_DTH    (3.14159265358979323846 / 720.0)
#define D_DPHI   (2.0 * 3.14159265358979323846 / 1440.0)
#define D_CUTOFF (2.0 * 3.14159265358979323846 / 720.0)

// Scratch state (allocation-free __device__ globals).
// Layout: field f in {h,u,v} at offset f*FOFF, then [b][lat][lon].
static __device__ float g_curA[3 * NB * NLAT * NLON];
static __device__ float g_curB[3 * NB * NLAT * NLON];
static __device__ float g_acc [3 * NB * NLAT * NLON];

__global__ void __launch_bounds__(BLOCK, 1)
tend_kernel(const float* __restrict__ h0,
            const float* __restrict__ uv0,
            const float* __restrict__ Kgc,
            const float* __restrict__ Kgs,
            const float* __restrict__ Kdc,
            const float* __restrict__ Kds,
            const float* __restrict__ fcor,
            float* __restrict__ outH,
            float* __restrict__ outUV,
            int stage)
{
    extern __shared__ float sh[];

    // Pole rows (full-circle loops) first in scheduling order.
    int bl = blockIdx.x;
    int l  = (bl & 1) ? (NLAT - 1 - (bl >> 1)) : (bl >> 1);
    int b  = blockIdx.y;

    // Stage source selection
    const float *sH, *sU, *sV;
    int uvStride;
    if (stage == 1) { sH = h0; sU = uv0; sV = uv0 + 1; uvStride = 2; }
    else {
        const float* c = (stage == 3) ? g_curB : g_curA;
        sH = c; sU = c + FOFF; sV = c + 2 * FOFF; uvStride = 1;
    }

    // ---- fill shared memory: 15 rows, circularly duplicated ----
    // sh[q] = x[(q - 720) mod 1440]; access x[(n+j)%1440] as sh[720+n+j].
    for (int e = threadIdx.x; e < NROWS * NLON; e += BLOCK) {
        int f  = e / (5 * NLON);
        int rr = (e / NLON) % 5;
        int m  = e % NLON;
        int lc = l + rr - 2;
        lc = lc < 0 ? 0 : (lc > NLAT - 1 ? NLAT - 1 : lc);
        const float* p = (f == 0) ? sH : (f == 1 ? sU : sV);
        int st = (f == 0) ? 1 : uvStride;
        float v = p[((size_t)(b * NLAT + lc) * NLON + m) * st];
        int q1 = m + 720; if (q1 >= NLON) q1 -= NLON;
        float* row = sh + (f * 5 + rr) * RSTRIDE;
        row[q1] = v;
        row[q1 + NLON] = v;
        if (q1 == 0) row[2 * NLON] = v;
    }
    __syncthreads();

    if (threadIdx.x >= NCOMP) return;
    int n0 = threadIdx.x * 4;

    float adu[4] = {0.f, 0.f, 0.f, 0.f};
    float adv[4] = {0.f, 0.f, 0.f, 0.f};
    float adh[4] = {0.f, 0.f, 0.f, 0.f};

    #pragma unroll
    for (int dd = 0; dd < 5; ++dd) {
        int lq = l + dd - 2;
        // out-of-range (invalid) and pole source rows (qw = sin = 0) contribute 0
        if (lq < 1 || lq > NLAT - 2) continue;

        // analytic support half-width (upper bound; zeros in K make overestimate safe)
        int jlo, cnt;
        double tp = (double)l  * D_DTH;
        double tq = (double)lq * D_DTH;
        if (l == 0 || l == NLAT - 1) {
            // output at pole: theta independent of phi
            if (fabs(tq - tp) < D_CUTOFF - 1e-9) { jlo = -NLON / 2; cnt = NLON; }
            else continue;
        } else {
            double sp = sin(tp), cp = cos(tp), sq = sin(tq), cq = cos(tq);
            double cph = (cos(D_CUTOFF) - cp * cq) / (sp * sq);
            if (cph >= 1.0) continue;
            int W = NLON / 2;
            if (cph > -1.0) W = (int)(acos(cph) / D_DPHI) + 2;
            if (W >= NLON / 2) { jlo = -NLON / 2; cnt = NLON; }
            else               { jlo = -W;        cnt = 2 * W + 1; }
        }

        int ko = (l * 5 + dd) * NLON;
        const float* kgc = Kgc + ko;
        const float* kgs = Kgs + ko;
        const float* kdc = Kdc + ko;
        const float* kds = Kds + ko;
        const float* shh = sh + (0 * 5 + dd) * RSTRIDE;
        const float* shu = sh + (1 * 5 + dd) * RSTRIDE;
        const float* shv = sh + (2 * 5 + dd) * RSTRIDE;

        int base = NLON / 2 + n0 + jlo;
        float wh[4], wu[4], wv[4];
        #pragma unroll
        for (int i = 0; i < 4; ++i) {
            wh[i] = shh[base + i];
            wu[i] = shu[base + i];
            wv[i] = shv[base + i];
        }
        int jm = jlo + NLON;   // in [720, 1439]

        #pragma unroll 4
        for (int j = 0; j < cnt; ++j) {
            float kc = __ldg(kgc + jm);
            float ks = __ldg(kgs + jm);
            float dc = __ldg(kdc + jm);
            float ds = __ldg(kds + jm);
            #pragma unroll
            for (int i = 0; i < 4; ++i) {
                adu[i] = fmaf(kc, wh[i], adu[i]);
                adv[i] = fmaf(ks, wh[i], adv[i]);
                adh[i] = fmaf(dc, wu[i], adh[i]);
                adh[i] = fmaf(ds, wv[i], adh[i]);
            }
            // slide windows
            wh[0] = wh[1]; wh[1] = wh[2]; wh[2] = wh[3]; wh[3] = shh[base + j + 4];
            wu[0] = wu[1]; wu[1] = wu[2]; wu[2] = wu[3]; wu[3] = shu[base + j + 4];
            wv[0] = wv[1]; wv[1] = wv[2]; wv[2] = wv[3]; wv[3] = shv[base + j + 4];
            if (++jm >= NLON) jm = 0;
        }
    }

    // ---- epilogue: tendency + fused RK4 combine ----
    float fl = __ldg(fcor + l);
    size_t rb = ((size_t)b * NLAT + l) * NLON + n0;
    const float* shu_c = sh + (1 * 5 + 2) * RSTRIDE + NLON / 2 + n0;
    const float* shv_c = sh + (2 * 5 + 2) * RSTRIDE + NLON / 2 + n0;

    float* dstH; float* dstU; float* dstV;
    if (stage == 1 || stage == 3) { dstH = g_curA; }
    else                          { dstH = g_curB; }
    dstU = dstH + FOFF; dstV = dstH + 2 * FOFF;

    #pragma unroll
    for (int i = 0; i < 4; ++i) {
        float uc = shu_c[i], vc = shv_c[i];
        float kh = -adh[i];                 // -H0 * div-corr, H0 = 1
        float ku = -adu[i] - fl * vc;       // -G * grad-corr - f v, G = 1
        float kv = -adv[i] + fl * uc;
        size_t idx = rb + i;

        float y0h = h0[idx];
        float y0u = uv0[2 * idx];
        float y0v = uv0[2 * idx + 1];

        if (stage == 4) {
            float oh = y0h + (DT / 6.f) * (g_acc[idx]            + kh);
            float ou = y0u + (DT / 6.f) * (g_acc[FOFF + idx]     + ku);
            float ov = y0v + (DT / 6.f) * (g_acc[2 * FOFF + idx] + kv);
            outH[idx] = oh;
            float2 o2; o2.x = ou; o2.y = ov;
            reinterpret_cast<float2*>(outUV)[idx] = o2;
        } else {
            if (stage == 1) {
                g_acc[idx]            = kh;
                g_acc[FOFF + idx]     = ku;
                g_acc[2 * FOFF + idx] = kv;
            } else {
                g_acc[idx]            += 2.f * kh;
                g_acc[FOFF + idx]     += 2.f * ku;
                g_acc[2 * FOFF + idx] += 2.f * kv;
            }
            float a = (stage == 3) ? DT : 0.5f * DT;
            dstH[idx] = y0h + a * kh;
            dstU[idx] = y0u + a * ku;
            dstV[idx] = y0v + a * kv;
        }
    }
}

extern "C" void kernel_launch(void* const* d_in, const int* in_sizes, int n_in,
                              void* d_out, int out_size)
{
    const float* h0  = (const float*)d_in[0];
    const float* uv0 = (const float*)d_in[1];
    const float* Kgc = (const float*)d_in[2];
    const float* Kgs = (const float*)d_in[3];
    const float* Kdc = (const float*)d_in[4];
    const float* Kds = (const float*)d_in[5];
    const float* fc  = (const float*)d_in[6];

    float* outH  = (float*)d_out;
    float* outUV = (float*)d_out + FOFF;   // (h_new, uv_new) flattened in order

    cudaFuncSetAttribute(tend_kernel,
                         cudaFuncAttributeMaxDynamicSharedMemorySize, SMEM_BYTES);

    dim3 grid(NLAT, NB), block(BLOCK);
    for (int stage = 1; stage <= 4; ++stage) {
        tend_kernel<<<grid, block, SMEM_BYTES>>>(h0, uv0, Kgc, Kgs, Kdc, Kds, fc,
                                                 outH, outUV, stage);
    }
    (void)in_sizes; (void)n_in; (void)out_size; (void)DTH;
}

// round 2
// speedup vs baseline: 1.0023x; 1.0023x over previous
#include <cuda_runtime.h>
#include <math.h>

#define NLAT 721
#define NLON 1440
#define NB   4
#define KOFF 2
#define DT   0.01f

#define FOFF   ((size_t)NB * NLAT * NLON)      // one field worth of elements
#define RSTRIDE 2884                            // padded duplicated row (need 2881)
#define NROWS  15                               // 3 fields x 5 lat offsets
#define BLOCK  384
#define NCOMP  360                              // computing threads (4 lons each)
#define SMEM_BYTES (NROWS * RSTRIDE * 4)

static const double DTH    = 3.14159265358979323846 / (NLAT - 1);
#define D_DTH    (3.14159265358979323846 / 720.0)
#define D_DPHI   (2.0 * 3.14159265358979323846 / 1440.0)
#define D_CUTOFF (2.0 * 3.14159265358979323846 / 720.0)

// Scratch state (allocation-free __device__ globals).
// Layout: field f in {h,u,v} at offset f*FOFF, then [b][lat][lon].
static __device__ float g_curA[3 * NB * NLAT * NLON];
static __device__ float g_curB[3 * NB * NLAT * NLON];
static __device__ float g_acc [3 * NB * NLAT * NLON];

__global__ void __launch_bounds__(BLOCK, 1)
tend_kernel(const float* __restrict__ h0,
            const float* __restrict__ uv0,
            const float* __restrict__ Kgc,
            const float* __restrict__ Kgs,
            const float* __restrict__ Kdc,
            const float* __restrict__ Kds,
            const float* __restrict__ fcor,
            float* __restrict__ outH,
            float* __restrict__ outUV,
            int stage)
{
    extern __shared__ float sh[];

    // Pole rows (full-circle loops) first in scheduling order.
    int bl = blockIdx.x;
    int l  = (bl & 1) ? (NLAT - 1 - (bl >> 1)) : (bl >> 1);
    int b  = blockIdx.y;

    // Stage source selection
    const float *sH, *sU, *sV;
    int uvStride;
    if (stage == 1) { sH = h0; sU = uv0; sV = uv0 + 1; uvStride = 2; }
    else {
        const float* c = (stage == 3) ? g_curB : g_curA;
        sH = c; sU = c + FOFF; sV = c + 2 * FOFF; uvStride = 1;
    }

    // ---- fill shared memory: 15 rows, circularly duplicated ----
    // sh[q] = x[(q - 720) mod 1440]; access x[(n+j)%1440] as sh[720+n+j].
    for (int e = threadIdx.x; e < NROWS * NLON; e += BLOCK) {
        int f  = e / (5 * NLON);
        int rr = (e / NLON) % 5;
        int m  = e % NLON;
        int lc = l + rr - 2;
        lc = lc < 0 ? 0 : (lc > NLAT - 1 ? NLAT - 1 : lc);
        const float* p = (f == 0) ? sH : (f == 1 ? sU : sV);
        int st = (f == 0) ? 1 : uvStride;
        float v = p[((size_t)(b * NLAT + lc) * NLON + m) * st];
        int q1 = m + 720; if (q1 >= NLON) q1 -= NLON;
        float* row = sh + (f * 5 + rr) * RSTRIDE;
        row[q1] = v;
        row[q1 + NLON] = v;
        if (q1 == 0) row[2 * NLON] = v;
    }
    __syncthreads();

    if (threadIdx.x >= NCOMP) return;
    int n0 = threadIdx.x * 4;

    float adu[4] = {0.f, 0.f, 0.f, 0.f};
    float adv[4] = {0.f, 0.f, 0.f, 0.f};
    float adh[4] = {0.f, 0.f, 0.f, 0.f};

    #pragma unroll
    for (int dd = 0; dd < 5; ++dd) {
        int lq = l + dd - 2;
        // out-of-range (invalid) and pole source rows (qw = sin = 0) contribute 0
        if (lq < 1 || lq > NLAT - 2) continue;

        // analytic support half-width (upper bound; zeros in K make overestimate safe)
        int jlo, cnt;
        double tp = (double)l  * D_DTH;
        double tq = (double)lq * D_DTH;
        if (l == 0 || l == NLAT - 1) {
            // output at pole: theta independent of phi
            if (fabs(tq - tp) < D_CUTOFF - 1e-9) { jlo = -NLON / 2; cnt = NLON; }
            else continue;
        } else {
            double sp = sin(tp), cp = cos(tp), sq = sin(tq), cq = cos(tq);
            double cph = (cos(D_CUTOFF) - cp * cq) / (sp * sq);
            if (cph >= 1.0) continue;
            int W = NLON / 2;
            if (cph > -1.0) W = (int)(acos(cph) / D_DPHI) + 2;
            if (W >= NLON / 2) { jlo = -NLON / 2; cnt = NLON; }
            else               { jlo = -W;        cnt = 2 * W + 1; }
        }

        int ko = (l * 5 + dd) * NLON;
        const float* kgc = Kgc + ko;
        const float* kgs = Kgs + ko;
        const float* kdc = Kdc + ko;
        const float* kds = Kds + ko;
        const float* shh = sh + (0 * 5 + dd) * RSTRIDE;
        const float* shu = sh + (1 * 5 + dd) * RSTRIDE;
        const float* shv = sh + (2 * 5 + dd) * RSTRIDE;

        int base = NLON / 2 + n0 + jlo;
        float wh[4], wu[4], wv[4];
        #pragma unroll
        for (int i = 0; i < 4; ++i) {
            wh[i] = shh[base + i];
            wu[i] = shu[base + i];
            wv[i] = shv[base + i];
        }
        int jm = jlo + NLON;   // in [720, 1439]

        #pragma unroll 4
        for (int j = 0; j < cnt; ++j) {
            float kc = __ldg(kgc + jm);
            float ks = __ldg(kgs + jm);
            float dc = __ldg(kdc + jm);
            float ds = __ldg(kds + jm);
            #pragma unroll
            for (int i = 0; i < 4; ++i) {
                adu[i] = fmaf(kc, wh[i], adu[i]);
                adv[i] = fmaf(ks, wh[i], adv[i]);
                adh[i] = fmaf(dc, wu[i], adh[i]);
                adh[i] = fmaf(ds, wv[i], adh[i]);
            }
            // slide windows
            wh[0] = wh[1]; wh[1] = wh[2]; wh[2] = wh[3]; wh[3] = shh[base + j + 4];
            wu[0] = wu[1]; wu[1] = wu[2]; wu[2] = wu[3]; wu[3] = shu[base + j + 4];
            wv[0] = wv[1]; wv[1] = wv[2]; wv[2] = wv[3]; wv[3] = shv[base + j + 4];
            if (++jm >= NLON) jm = 0;
        }
    }

    // ---- epilogue: tendency + fused RK4 combine ----
    float fl = __ldg(fcor + l);
    size_t rb = ((size_t)b * NLAT + l) * NLON + n0;
    const float* shu_c = sh + (1 * 5 + 2) * RSTRIDE + NLON / 2 + n0;
    const float* shv_c = sh + (2 * 5 + 2) * RSTRIDE + NLON / 2 + n0;

    float* dstH; float* dstU; float* dstV;
    if (stage == 1 || stage == 3) { dstH = g_curA; }
    else                          { dstH = g_curB; }
    dstU = dstH + FOFF; dstV = dstH + 2 * FOFF;

    #pragma unroll
    for (int i = 0; i < 4; ++i) {
        float uc = shu_c[i], vc = shv_c[i];
        float kh = -adh[i];                 // -H0 * div-corr, H0 = 1
        float ku = -adu[i] - fl * vc;       // -G * grad-corr - f v, G = 1
        float kv = -adv[i] + fl * uc;
        size_t idx = rb + i;

        float y0h = h0[idx];
        float y0u = uv0[2 * idx];
        float y0v = uv0[2 * idx + 1];

        if (stage == 4) {
            float oh = y0h + (DT / 6.f) * (g_acc[idx]            + kh);
            float ou = y0u + (DT / 6.f) * (g_acc[FOFF + idx]     + ku);
            float ov = y0v + (DT / 6.f) * (g_acc[2 * FOFF + idx] + kv);
            outH[idx] = oh;
            float2 o2; o2.x = ou; o2.y = ov;
            reinterpret_cast<float2*>(outUV)[idx] = o2;
        } else {
            if (stage == 1) {
                g_acc[idx]            = kh;
                g_acc[FOFF + idx]     = ku;
                g_acc[2 * FOFF + idx] = kv;
            } else {
                g_acc[idx]            += 2.f * kh;
                g_acc[FOFF + idx]     += 2.f * ku;
                g_acc[2 * FOFF + idx] += 2.f * kv;
            }
            float a = (stage == 3) ? DT : 0.5f * DT;
            dstH[idx] = y0h + a * kh;
            dstU[idx] = y0u + a * ku;
            dstV[idx] = y0v + a * kv;
        }
    }
}

extern "C" void kernel_launch(void* const* d_in, const int* in_sizes, int n_in,
                              void* d_out, int out_size)
{
    const float* h0  = (const float*)d_in[0];
    const float* uv0 = (const float*)d_in[1];
    const float* Kgc = (const float*)d_in[2];
    const float* Kgs = (const float*)d_in[3];
    const float* Kdc = (const float*)d_in[4];
    const float* Kds = (const float*)d_in[5];
    const float* fc  = (const float*)d_in[6];

    float* outH  = (float*)d_out;
    float* outUV = (float*)d_out + FOFF;   // (h_new, uv_new) flattened in order

    cudaFuncSetAttribute(tend_kernel,
                         cudaFuncAttributeMaxDynamicSharedMemorySize, SMEM_BYTES);

    dim3 grid(NLAT, NB), block(BLOCK);
    for (int stage = 1; stage <= 4; ++stage) {
        tend_kernel<<<grid, block, SMEM_BYTES>>>(h0, uv0, Kgc, Kgs, Kdc, Kds, fc,
                                                 outH, outUV, stage);
    }
    (void)in_sizes; (void)n_in; (void)out_size; (void)DTH;
}

// round 3
// speedup vs baseline: 4.6196x; 4.6092x over previous
#include <cuda_runtime.h>
#include <math.h>

#define NLAT 721
#define NLON 1440
#define NB   4
#define DT   0.01f
#define FOFF ((size_t)NB * NLAT * NLON)
#define DTH  (3.14159265358979323846 / 720.0)

#define LS     20
#define NPOLAR 40
#define NINT   (NLAT - NPOLAR)
#define NCHB   8
#define NSLOT  (3 * NCHB)

#define TILE   720
#define HALO   32
#define SMW_A  (TILE + 2 * HALO + 8)
#define BLK_A  192
#define COMP_A 180

#define SMW_B  2896
#define BLK_B  384

static __device__ float g_curA[3 * FOFF];
static __device__ float g_curB[3 * FOFF];
static __device__ float g_acc [3 * FOFF];
static __device__ float g_part[(size_t)NSLOT * NB * NPOLAR * 3 * NLON];

__device__ __forceinline__ int polar_map(int rl) { return rl < 20 ? rl : 701 + (rl - 20); }

// Support bounds for lat-offset dd in {0,1,2} (lq = l-1+dd). jl 4-aligned,
// cnt multiple of 4. Overestimate is safe: K is zero outside true support.
__device__ void compute_params(int l, int dd, int cap, int* jl, int* cnt, int* valid)
{
    *valid = 0;
    int lq = l - 1 + dd;
    if (lq < 1 || lq > NLAT - 2) return;            // pole sources: qw = 0
    if (l == 0 || l == NLAT - 1) {                  // pole outputs: full circle
        if (fabs((double)(lq - l)) * DTH < 2.0 * DTH - 1e-9) {
            *jl = -720; *cnt = 1440; *valid = 1;
        }
        return;
    }
    double tp = l * DTH, tq = lq * DTH;
    double sp = sin(tp), cp = cos(tp), sq = sin(tq), cq = cos(tq);
    double cph = (cos(2.0 * DTH) - cp * cq) / (sp * sq);
    if (cph >= 1.0) return;
    int W = 720;
    if (cph > -1.0) W = (int)(acos(cph) / DTH) + 2;
    int Wa = (W + 3) & ~3;
    if (Wa > cap) Wa = cap;
    if (Wa >= 720) { *jl = -720; *cnt = 1440; }
    else           { *jl = -Wa;  *cnt = 2 * Wa + 4; }
    *valid = 1;
}

struct Acc { float adu[4], adv[4], adh[4]; };

// Correlation over j in [j0, j1), 4-aligned. rh/ru/rv: smem rows pre-offset so
// element j = x[n0 + j]. K tap weight at kR[koff + j] (linear, no wrap).
__device__ __forceinline__ void seg_loop(
    const float* __restrict__ kgc, const float* __restrict__ kgs,
    const float* __restrict__ kdc, const float* __restrict__ kds,
    const float* rh, const float* ru, const float* rv,
    int j0, int j1, int koff, Acc& a)
{
    if (j0 >= j1) return;
    float4 hA = *(const float4*)(rh + j0);
    float4 uA = *(const float4*)(ru + j0);
    float4 vA = *(const float4*)(rv + j0);
    for (int j = j0; j < j1; j += 4) {
        const float4 kc = *(const float4*)(kgc + koff + j);
        const float4 ks = *(const float4*)(kgs + koff + j);
        const float4 dc = *(const float4*)(kdc + koff + j);
        const float4 dz = *(const float4*)(kds + koff + j);
        float4 hB = *(const float4*)(rh + j + 4);
        float4 uB = *(const float4*)(ru + j + 4);
        float4 vB = *(const float4*)(rv + j + 4);
        float hb[8] = {hA.x,hA.y,hA.z,hA.w,hB.x,hB.y,hB.z,hB.w};
        float ub[8] = {uA.x,uA.y,uA.z,uA.w,uB.x,uB.y,uB.z,uB.w};
        float vb[8] = {vA.x,vA.y,vA.z,vA.w,vB.x,vB.y,vB.z,vB.w};
        float kcb[4] = {kc.x,kc.y,kc.z,kc.w};
        float ksb[4] = {ks.x,ks.y,ks.z,ks.w};
        float dcb[4] = {dc.x,dc.y,dc.z,dc.w};
        float dsb[4] = {dz.x,dz.y,dz.z,dz.w};
        #pragma unroll
        for (int jj = 0; jj < 4; ++jj)
            #pragma unroll
            for (int i = 0; i < 4; ++i) {
                a.adu[i] = fmaf(kcb[jj], hb[jj+i], a.adu[i]);
                a.adv[i] = fmaf(ksb[jj], hb[jj+i], a.adv[i]);
                a.adh[i] = fmaf(dcb[jj], ub[jj+i], a.adh[i]);
                a.adh[i] = fmaf(dsb[jj], vb[jj+i], a.adh[i]);
            }
        hA = hB; uA = uB; vA = vB;
    }
}

__device__ __forceinline__ void rk_epilogue(
    int stage, size_t idx, float kh, float ku, float kv,
    const float* __restrict__ h0, const float* __restrict__ uv0,
    float* __restrict__ outH, float* __restrict__ outUV)
{
    float y0h = h0[idx], y0u = uv0[2*idx], y0v = uv0[2*idx+1];
    if (stage == 4) {
        outH[idx] = y0h + (DT/6.f) * (g_acc[idx] + kh);
        float2 o;
        o.x = y0u + (DT/6.f) * (g_acc[FOFF + idx]   + ku);
        o.y = y0v + (DT/6.f) * (g_acc[2*FOFF + idx] + kv);
        reinterpret_cast<float2*>(outUV)[idx] = o;
    } else {
        if (stage == 1) {
            g_acc[idx] = kh; g_acc[FOFF+idx] = ku; g_acc[2*FOFF+idx] = kv;
        } else {
            g_acc[idx] += 2.f*kh; g_acc[FOFF+idx] += 2.f*ku; g_acc[2*FOFF+idx] += 2.f*kv;
        }
        float aa = (stage == 3) ? DT : 0.5f * DT;
        float* dst = (stage == 2) ? g_curB : g_curA;
        dst[idx] = y0h + aa*kh; dst[FOFF+idx] = y0u + aa*ku; dst[2*FOFF+idx] = y0v + aa*kv;
    }
}

#define SRC_SELECT()                                                          \
    const float *srcH, *srcU, *srcV; int us;                                  \
    if (stage == 1) { srcH = h0; srcU = uv0; srcV = uv0 + 1; us = 2; }        \
    else { const float* c_ = (stage == 3) ? g_curB : g_curA;                  \
           srcH = c_; srcU = c_ + FOFF; srcV = c_ + 2*FOFF; us = 1; }

// ------------- interior lats: one block per (b, l, lon-tile) ---------------
__global__ void __launch_bounds__(BLK_A)
tendA_kernel(const float* __restrict__ h0, const float* __restrict__ uv0,
             const float* __restrict__ Kgc, const float* __restrict__ Kgs,
             const float* __restrict__ Kdc, const float* __restrict__ Kds,
             const float* __restrict__ fcor,
             float* __restrict__ outH, float* __restrict__ outUV, int stage)
{
    __shared__ __align__(16) float sh[9 * SMW_A];
    __shared__ int p_jl[3], p_cnt[3], p_valid[3];

    int tid = threadIdx.x, bx = blockIdx.x, b = blockIdx.y;
    int tile = bx & 1, li = bx >> 1;
    int l = (li & 1) ? (700 - (li >> 1)) : (LS + (li >> 1));  // heavy rows first
    int t0 = tile * TILE;

    if (tid < 3) compute_params(l, tid, HALO - 4, &p_jl[tid], &p_cnt[tid], &p_valid[tid]);

    SRC_SELECT();
    int base_m = t0 - HALO;
    for (int e = tid; e < 9 * SMW_A; e += BLK_A) {
        int r = e / SMW_A, q = e - r * SMW_A;
        int f = r / 3, dd = r - f * 3;
        int lq = l - 1 + dd;
        int m = base_m + q;
        m += (m < 0) ? NLON : 0; m -= (m >= NLON) ? NLON : 0;
        size_t g = (size_t)(b * NLAT + lq) * NLON + m;
        sh[e] = (f == 0) ? srcH[g] : (f == 1 ? srcU[g*us] : srcV[g*us]);
    }
    __syncthreads();
    if (tid >= COMP_A) return;

    Acc a; 
    #pragma unroll
    for (int i = 0; i < 4; ++i) { a.adu[i]=0.f; a.adv[i]=0.f; a.adh[i]=0.f; }
    int n0 = tid * 4, off0 = HALO + n0;

    for (int dd = 0; dd < 3; ++dd) {
        if (!p_valid[dd]) continue;
        int jl = p_jl[dd], j1 = jl + p_cnt[dd];
        const float* rh = sh + (0*3 + dd) * SMW_A + off0;
        const float* ru = sh + (1*3 + dd) * SMW_A + off0;
        const float* rv = sh + (2*3 + dd) * SMW_A + off0;
        size_t ko = (size_t)(l * 5 + dd + 1) * NLON;
        seg_loop(Kgc+ko, Kgs+ko, Kdc+ko, Kds+ko, rh, ru, rv, jl, 0, NLON, a);
        seg_loop(Kgc+ko, Kgs+ko, Kdc+ko, Kds+ko, rh, ru, rv, 0, j1, 0, a);
    }

    float fl = __ldg(fcor + l);
    const float* cu = sh + (1*3 + 1) * SMW_A + off0;
    const float* cv = sh + (2*3 + 1) * SMW_A + off0;
    size_t rb = (size_t)(b * NLAT + l) * NLON + t0 + n0;
    #pragma unroll
    for (int i = 0; i < 4; ++i)
        rk_epilogue(stage, rb + i, -a.adh[i], -a.adu[i] - fl*cv[i],
                    -a.adv[i] + fl*cu[i], h0, uv0, outH, outUV);
}

// ------------- polar rows: per-(row, dd, j-chunk) partial sums --------------
__global__ void __launch_bounds__(BLK_B)
tendB_kernel(const float* __restrict__ h0, const float* __restrict__ uv0,
             const float* __restrict__ Kgc, const float* __restrict__ Kgs,
             const float* __restrict__ Kdc, const float* __restrict__ Kds,
             int stage)
{
    __shared__ __align__(16) float sh[3 * SMW_B];
    __shared__ int p[3];

    int tid = threadIdx.x, bx = blockIdx.x, b = blockIdx.y;
    int rl = bx / (3 * NCHB), rem = bx - rl * 3 * NCHB;
    int dd = rem / NCHB, c = rem - dd * NCHB;
    int l = polar_map(rl);

    if (tid == 0) compute_params(l, dd, 720, &p[0], &p[1], &p[2]);
    __syncthreads();

    int task = b * NPOLAR + rl;
    float* part = g_part + ((size_t)(dd * NCHB + c) * (NB * NPOLAR) + task) * (3 * NLON);

    int jA = 0, jB = 0; bool act = false;
    if (p[2]) {
        int steps = p[1] >> 2, per = (steps + NCHB - 1) / NCHB;
        int s0 = c * per, s1 = min(steps, s0 + per);
        if (s0 < s1) { act = true; jA = p[0] + 4*s0; jB = p[0] + 4*s1; }
    }
    if (!act) { for (int e = tid; e < 3*NLON; e += BLK_B) part[e] = 0.f; return; }

    int lq = l - 1 + dd;
    SRC_SELECT();
    for (int e = tid; e < 3 * NLON; e += BLK_B) {
        int f = e / NLON, m = e - f * NLON;
        size_t g = (size_t)(b * NLAT + lq) * NLON + m;
        float v = (f == 0) ? srcH[g] : (f == 1 ? srcU[g*us] : srcV[g*us]);
        int q = m + 720; if (q >= NLON) q -= NLON;
        sh[f * SMW_B + q] = v;
        sh[f * SMW_B + q + NLON] = v;
    }
    __syncthreads();
    if (tid >= 360) return;

    int n0 = tid * 4;
    Acc a;
    #pragma unroll
    for (int i = 0; i < 4; ++i) { a.adu[i]=0.f; a.adv[i]=0.f; a.adh[i]=0.f; }
    const float* rh = sh + 720 + n0;
    const float* ru = sh + SMW_B + 720 + n0;
    const float* rv = sh + 2*SMW_B + 720 + n0;
    size_t ko = (size_t)(l * 5 + dd + 1) * NLON;
    seg_loop(Kgc+ko, Kgs+ko, Kdc+ko, Kds+ko, rh, ru, rv, jA, min(jB,0), NLON, a);
    seg_loop(Kgc+ko, Kgs+ko, Kdc+ko, Kds+ko, rh, ru, rv, max(jA,0), jB, 0, a);

    #pragma unroll
    for (int i = 0; i < 4; ++i) {
        part[0*NLON + n0 + i] = a.adu[i];
        part[1*NLON + n0 + i] = a.adv[i];
        part[2*NLON + n0 + i] = a.adh[i];
    }
}

__global__ void __launch_bounds__(384)
reduceB_kernel(const float* __restrict__ h0, const float* __restrict__ uv0,
               const float* __restrict__ fcor,
               float* __restrict__ outH, float* __restrict__ outUV, int stage)
{
    int tid = threadIdx.x;
    if (tid >= 360) return;
    int rl = blockIdx.x, b = blockIdx.y;
    int l = polar_map(rl);
    int task = b * NPOLAR + rl;
    int n0 = tid * 4;

    float su[4] = {0,0,0,0}, sv[4] = {0,0,0,0}, sk[4] = {0,0,0,0};
    for (int s = 0; s < NSLOT; ++s) {
        const float* part = g_part + ((size_t)s * (NB * NPOLAR) + task) * (3 * NLON);
        float4 x = *(const float4*)(part + n0);
        float4 y = *(const float4*)(part + NLON + n0);
        float4 z = *(const float4*)(part + 2*NLON + n0);
        su[0]+=x.x; su[1]+=x.y; su[2]+=x.z; su[3]+=x.w;
        sv[0]+=y.x; sv[1]+=y.y; sv[2]+=y.z; sv[3]+=y.w;
        sk[0]+=z.x; sk[1]+=z.y; sk[2]+=z.z; sk[3]+=z.w;
    }
    SRC_SELECT();
    float fl = __ldg(fcor + l);
    size_t rb = (size_t)(b * NLAT + l) * NLON + n0;
    #pragma unroll
    for (int i = 0; i < 4; ++i) {
        size_t g = rb + i;
        float uc = srcU[g*us], vc = srcV[g*us];
        rk_epilogue(stage, g, -sk[i], -su[i] - fl*vc, -sv[i] + fl*uc,
                    h0, uv0, outH, outUV);
    }
}

extern "C" void kernel_launch(void* const* d_in, const int* in_sizes, int n_in,
                              void* d_out, int out_size)
{
    const float* h0  = (const float*)d_in[0];
    const float* uv0 = (const float*)d_in[1];
    const float* Kgc = (const float*)d_in[2];
    const float* Kgs = (const float*)d_in[3];
    const float* Kdc = (const float*)d_in[4];
    const float* Kds = (const float*)d_in[5];
    const float* fc  = (const float*)d_in[6];
    float* outH  = (float*)d_out;
    float* outUV = (float*)d_out + FOFF;

    for (int stage = 1; stage <= 4; ++stage) {
        tendB_kernel<<<dim3(NPOLAR * 3 * NCHB, NB), BLK_B>>>(h0, uv0, Kgc, Kgs, Kdc, Kds, stage);
        tendA_kernel<<<dim3(NINT * 2, NB), BLK_A>>>(h0, uv0, Kgc, Kgs, Kdc, Kds, fc, outH, outUV, stage);
        reduceB_kernel<<<dim3(NPOLAR, NB), 384>>>(h0, uv0, fc, outH, outUV, stage);
    }
    (void)in_sizes; (void)n_in; (void)out_size;
}

// round 4
// speedup vs baseline: 5.7355x; 1.2415x over previous
#include <cuda_runtime.h>
#include <math.h>

#define NLAT 721
#define NLON 1440
#define NB   4
#define DT   0.01f
#define FOFF ((size_t)NB * NLAT * NLON)
#define DTH  (3.14159265358979323846 / 720.0)

#define LS     20
#define NPOLAR 40
#define NINT   (NLAT - NPOLAR)
#define NCHB   8

#define TILE   720
#define HALO   32
#define SMW_A  (TILE + 2 * HALO + 8)
#define BLK_A  192
#define COMP_A 180

#define SMW_B  2896
#define BLK_B  384

static __device__ float g_curA[3 * FOFF];
static __device__ float g_curB[3 * FOFF];
static __device__ float g_acc [3 * FOFF];
static __device__ float g_part[(size_t)(3 * NCHB) * NB * NPOLAR * 3 * NLON];
static __device__ int   g_bjl [NLAT * 3];
static __device__ int   g_bcnt[NLAT * 3];

__device__ __forceinline__ int polar_map(int rl) { return rl < 20 ? rl : 701 + (rl - 20); }

// One-shot: exact support bounds per (l, dd). jl 4-aligned down, end 4-aligned
// up; padded taps multiply exact zeros in K, so overestimate is safe.
__global__ void init_bounds()
{
    int idx = blockIdx.x * blockDim.x + threadIdx.x;
    if (idx >= NLAT * 3) return;
    int l = idx / 3, dd = idx - 3 * l;
    int jl = 0, cnt = 0;
    int lq = l - 1 + dd;
    if (lq >= 1 && lq <= NLAT - 2) {
        if (l == 0 || l == NLAT - 1) { jl = -720; cnt = 1440; }
        else {
            double tp = l * DTH, tq = lq * DTH;
            double cph = (cos(2.0 * DTH) - cos(tp) * cos(tq)) / (sin(tp) * sin(tq));
            if (cph < 1.0) {
                int W = 720;
                if (cph > -1.0) W = (int)(acos(cph) / DTH) + 1;
                if (W >= 716) { jl = -720; cnt = 1440; }
                else { jl = -((W + 3) & ~3); int je = (W + 4) & ~3; cnt = je - jl; }
            }
        }
    }
    g_bjl[idx] = jl; g_bcnt[idx] = cnt;
}

struct Acc { float adu[4], adv[4], adh[4]; };

// Correlation over j in [j0, j1), 4-aligned. rh/ru/rv pre-offset so element
// j = x[n0 + j]. K tap at k*[koff + j] (linear segment, no wrap inside).
__device__ __forceinline__ void seg_loop(
    const float* __restrict__ kgc, const float* __restrict__ kgs,
    const float* __restrict__ kdc, const float* __restrict__ kds,
    const float* rh, const float* ru, const float* rv,
    int j0, int j1, int koff, Acc& a)
{
    if (j0 >= j1) return;
    float4 hA = *(const float4*)(rh + j0);
    float4 uA = *(const float4*)(ru + j0);
    float4 vA = *(const float4*)(rv + j0);
    for (int j = j0; j < j1; j += 4) {
        const float4 kc = *(const float4*)(kgc + koff + j);
        const float4 ks = *(const float4*)(kgs + koff + j);
        const float4 dc = *(const float4*)(kdc + koff + j);
        const float4 dz = *(const float4*)(kds + koff + j);
        float4 hB = *(const float4*)(rh + j + 4);
        float4 uB = *(const float4*)(ru + j + 4);
        float4 vB = *(const float4*)(rv + j + 4);
        float hb[8] = {hA.x,hA.y,hA.z,hA.w,hB.x,hB.y,hB.z,hB.w};
        float ub[8] = {uA.x,uA.y,uA.z,uA.w,uB.x,uB.y,uB.z,uB.w};
        float vb[8] = {vA.x,vA.y,vA.z,vA.w,vB.x,vB.y,vB.z,vB.w};
        float kcb[4] = {kc.x,kc.y,kc.z,kc.w};
        float ksb[4] = {ks.x,ks.y,ks.z,ks.w};
        float dcb[4] = {dc.x,dc.y,dc.z,dc.w};
        float dsb[4] = {dz.x,dz.y,dz.z,dz.w};
        #pragma unroll
        for (int jj = 0; jj < 4; ++jj)
            #pragma unroll
            for (int i = 0; i < 4; ++i) {
                a.adu[i] = fmaf(kcb[jj], hb[jj+i], a.adu[i]);
                a.adv[i] = fmaf(ksb[jj], hb[jj+i], a.adv[i]);
                a.adh[i] = fmaf(dcb[jj], ub[jj+i], a.adh[i]);
                a.adh[i] = fmaf(dsb[jj], vb[jj+i], a.adh[i]);
            }
        hA = hB; uA = uB; vA = vB;
    }
}

__device__ __forceinline__ void rk_epilogue(
    int stage, size_t idx, float kh, float ku, float kv,
    const float* __restrict__ h0, const float* __restrict__ uv0,
    float* __restrict__ outH, float* __restrict__ outUV)
{
    float y0h = h0[idx], y0u = uv0[2*idx], y0v = uv0[2*idx+1];
    if (stage == 4) {
        outH[idx] = y0h + (DT/6.f) * (g_acc[idx] + kh);
        float2 o;
        o.x = y0u + (DT/6.f) * (g_acc[FOFF + idx]   + ku);
        o.y = y0v + (DT/6.f) * (g_acc[2*FOFF + idx] + kv);
        reinterpret_cast<float2*>(outUV)[idx] = o;
    } else {
        if (stage == 1) {
            g_acc[idx] = kh; g_acc[FOFF+idx] = ku; g_acc[2*FOFF+idx] = kv;
        } else {
            g_acc[idx] += 2.f*kh; g_acc[FOFF+idx] += 2.f*ku; g_acc[2*FOFF+idx] += 2.f*kv;
        }
        float aa = (stage == 3) ? DT : 0.5f * DT;
        float* dst = (stage == 2) ? g_curB : g_curA;
        dst[idx] = y0h + aa*kh; dst[FOFF+idx] = y0u + aa*ku; dst[2*FOFF+idx] = y0v + aa*kv;
    }
}

#define SRC_SELECT()                                                          \
    const float *srcH, *srcU, *srcV; int us;                                  \
    if (stage == 1) { srcH = h0; srcU = uv0; srcV = uv0 + 1; us = 2; }        \
    else { const float* c_ = (stage == 3) ? g_curB : g_curA;                  \
           srcH = c_; srcU = c_ + FOFF; srcV = c_ + 2*FOFF; us = 1; }

// ------------- interior lats: one block per (b, l, lon-tile) ---------------
__global__ void __launch_bounds__(BLK_A)
tendA_kernel(const float* __restrict__ h0, const float* __restrict__ uv0,
             const float* __restrict__ Kgc, const float* __restrict__ Kgs,
             const float* __restrict__ Kdc, const float* __restrict__ Kds,
             const float* __restrict__ fcor,
             float* __restrict__ outH, float* __restrict__ outUV, int stage)
{
    __shared__ __align__(16) float sh[9 * SMW_A];

    int tid = threadIdx.x, bx = blockIdx.x, b = blockIdx.y;
    int tile = bx & 1, li = bx >> 1;
    int l = (li & 1) ? (700 - (li >> 1)) : (LS + (li >> 1));  // heavy rows first
    int t0 = tile * TILE;

    SRC_SELECT();
    int base_m = t0 - HALO;
    for (int e = tid; e < 9 * SMW_A; e += BLK_A) {
        int r = e / SMW_A, q = e - r * SMW_A;
        int f = r / 3, dd = r - f * 3;
        int lq = l - 1 + dd;
        int m = base_m + q;
        m += (m < 0) ? NLON : 0; m -= (m >= NLON) ? NLON : 0;
        size_t g = (size_t)(b * NLAT + lq) * NLON + m;
        sh[e] = (f == 0) ? srcH[g] : (f == 1 ? srcU[g*us] : srcV[g*us]);
    }
    __syncthreads();
    if (tid >= COMP_A) return;

    Acc a;
    #pragma unroll
    for (int i = 0; i < 4; ++i) { a.adu[i]=0.f; a.adv[i]=0.f; a.adh[i]=0.f; }
    int n0 = tid * 4, off0 = HALO + n0;

    for (int dd = 0; dd < 3; ++dd) {
        int cnt = g_bcnt[l * 3 + dd];
        if (cnt == 0) continue;
        int jl = g_bjl[l * 3 + dd];
        int je = jl + cnt;
        jl = max(jl, -(HALO - 4)); je = min(je, HALO - 4);   // defensive clamp
        const float* rh = sh + (0*3 + dd) * SMW_A + off0;
        const float* ru = sh + (1*3 + dd) * SMW_A + off0;
        const float* rv = sh + (2*3 + dd) * SMW_A + off0;
        size_t ko = (size_t)(l * 5 + dd + 1) * NLON;
        seg_loop(Kgc+ko, Kgs+ko, Kdc+ko, Kds+ko, rh, ru, rv, jl, min(je, 0), NLON, a);
        seg_loop(Kgc+ko, Kgs+ko, Kdc+ko, Kds+ko, rh, ru, rv, max(jl, 0), je, 0, a);
    }

    float fl = __ldg(fcor + l);
    const float* cu = sh + (1*3 + 1) * SMW_A + off0;
    const float* cv = sh + (2*3 + 1) * SMW_A + off0;
    size_t rb = (size_t)(b * NLAT + l) * NLON + t0 + n0;
    #pragma unroll
    for (int i = 0; i < 4; ++i)
        rk_epilogue(stage, rb + i, -a.adh[i], -a.adu[i] - fl*cv[i],
                    -a.adv[i] + fl*cu[i], h0, uv0, outH, outUV);
}

// ------------- polar rows: per-(row, dd, j-chunk) partial sums --------------
__global__ void __launch_bounds__(BLK_B)
tendB_kernel(const float* __restrict__ h0, const float* __restrict__ uv0,
             const float* __restrict__ Kgc, const float* __restrict__ Kgs,
             const float* __restrict__ Kdc, const float* __restrict__ Kds,
             int stage)
{
    __shared__ __align__(16) float sh[3 * SMW_B];

    int tid = threadIdx.x, bx = blockIdx.x, b = blockIdx.y;
    int rl = bx / (3 * NCHB), rem = bx - rl * 3 * NCHB;
    int dd = rem / NCHB, c = rem - dd * NCHB;
    int l = polar_map(rl);

    int cnt = g_bcnt[l * 3 + dd];
    if (cnt == 0) return;                       // reduceB skips these slots
    int jl = g_bjl[l * 3 + dd];
    int steps = cnt >> 2;
    int per = (steps + NCHB - 1) / NCHB;
    int s0 = c * per, s1 = min(steps, s0 + per);
    if (s0 >= s1) return;
    int jA = jl + 4 * s0, jB = jl + 4 * s1;

    int lq = l - 1 + dd;
    SRC_SELECT();
    for (int e = tid; e < 3 * NLON; e += BLK_B) {
        int f = e / NLON, m = e - f * NLON;
        size_t g = (size_t)(b * NLAT + lq) * NLON + m;
        float v = (f == 0) ? srcH[g] : (f == 1 ? srcU[g*us] : srcV[g*us]);
        int q = m + 720; if (q >= NLON) q -= NLON;
        sh[f * SMW_B + q] = v;
        sh[f * SMW_B + q + NLON] = v;
    }
    __syncthreads();
    if (tid >= 360) return;

    int n0 = tid * 4;
    Acc a;
    #pragma unroll
    for (int i = 0; i < 4; ++i) { a.adu[i]=0.f; a.adv[i]=0.f; a.adh[i]=0.f; }
    const float* rh = sh + 720 + n0;
    const float* ru = sh + SMW_B + 720 + n0;
    const float* rv = sh + 2*SMW_B + 720 + n0;
    size_t ko = (size_t)(l * 5 + dd + 1) * NLON;
    seg_loop(Kgc+ko, Kgs+ko, Kdc+ko, Kds+ko, rh, ru, rv, jA, min(jB,0), NLON, a);
    seg_loop(Kgc+ko, Kgs+ko, Kdc+ko, Kds+ko, rh, ru, rv, max(jA,0), jB, 0, a);

    int task = b * NPOLAR + rl;
    float* part = g_part + ((size_t)(dd * NCHB + c) * (NB * NPOLAR) + task) * (3 * NLON);
    #pragma unroll
    for (int i = 0; i < 4; ++i) {
        part[0*NLON + n0 + i] = a.adu[i];
        part[1*NLON + n0 + i] = a.adv[i];
        part[2*NLON + n0 + i] = a.adh[i];
    }
}

__global__ void __launch_bounds__(384)
reduceB_kernel(const float* __restrict__ h0, const float* __restrict__ uv0,
               const float* __restrict__ fcor,
               float* __restrict__ outH, float* __restrict__ outUV, int stage)
{
    int tid = threadIdx.x;
    if (tid >= 360) return;
    int rl = blockIdx.x, b = blockIdx.y;
    int l = polar_map(rl);
    int task = b * NPOLAR + rl;
    int n0 = tid * 4;

    float su[4] = {0,0,0,0}, sv[4] = {0,0,0,0}, sk[4] = {0,0,0,0};
    for (int dd = 0; dd < 3; ++dd) {
        int cnt = g_bcnt[l * 3 + dd];
        if (cnt == 0) continue;
        int steps = cnt >> 2;
        int per = (steps + NCHB - 1) / NCHB;
        int nact = (steps + per - 1) / per;
        for (int s = 0; s < nact; ++s) {
            const float* part = g_part +
                ((size_t)(dd * NCHB + s) * (NB * NPOLAR) + task) * (3 * NLON);
            float4 x = *(const float4*)(part + n0);
            float4 y = *(const float4*)(part + NLON + n0);
            float4 z = *(const float4*)(part + 2*NLON + n0);
            su[0]+=x.x; su[1]+=x.y; su[2]+=x.z; su[3]+=x.w;
            sv[0]+=y.x; sv[1]+=y.y; sv[2]+=y.z; sv[3]+=y.w;
            sk[0]+=z.x; sk[1]+=z.y; sk[2]+=z.z; sk[3]+=z.w;
        }
    }
    SRC_SELECT();
    float fl = __ldg(fcor + l);
    size_t rb = (size_t)(b * NLAT + l) * NLON + n0;
    #pragma unroll
    for (int i = 0; i < 4; ++i) {
        size_t g = rb + i;
        float uc = srcU[g*us], vc = srcV[g*us];
        rk_epilogue(stage, g, -sk[i], -su[i] - fl*vc, -sv[i] + fl*uc,
                    h0, uv0, outH, outUV);
    }
}

extern "C" void kernel_launch(void* const* d_in, const int* in_sizes, int n_in,
                              void* d_out, int out_size)
{
    const float* h0  = (const float*)d_in[0];
    const float* uv0 = (const float*)d_in[1];
    const float* Kgc = (const float*)d_in[2];
    const float* Kgs = (const float*)d_in[3];
    const float* Kdc = (const float*)d_in[4];
    const float* Kds = (const float*)d_in[5];
    const float* fc  = (const float*)d_in[6];
    float* outH  = (float*)d_out;
    float* outUV = (float*)d_out + FOFF;

    init_bounds<<<(NLAT * 3 + 127) / 128, 128>>>();

    for (int stage = 1; stage <= 4; ++stage) {
        tendB_kernel<<<dim3(NPOLAR * 3 * NCHB, NB), BLK_B>>>(h0, uv0, Kgc, Kgs, Kdc, Kds, stage);
        tendA_kernel<<<dim3(NINT * 2, NB), BLK_A>>>(h0, uv0, Kgc, Kgs, Kdc, Kds, fc, outH, outUV, stage);
        reduceB_kernel<<<dim3(NPOLAR, NB), 384>>>(h0, uv0, fc, outH, outUV, stage);
    }
    (void)in_sizes; (void)n_in; (void)out_size;
}

// round 5
// speedup vs baseline: 7.8471x; 1.3682x over previous
#include <cuda_runtime.h>
#include <math.h>

#define NLAT 721
#define NLON 1440
#define NB   4
#define DT   0.01f
#define FOFF ((size_t)NB * NLAT * NLON)
#define DTH  (3.14159265358979323846 / 720.0)

#define LS     20
#define NPOLAR 40
#define NINT   (NLAT - NPOLAR)
#define NCHB   8

#define TILE   720
#define HALO   32
#define SMW_A  (TILE + 2 * HALO + 8)   // 808, 16B-aligned rows
#define NF4_A  (SMW_A / 4)             // 202
#define BLK_A  192
#define COMP_A 180

#define SMW_B  2896
#define BLK_B  384

static __device__ float g_curA[3 * FOFF];
static __device__ float g_curB[3 * FOFF];
static __device__ float g_acc [3 * FOFF];
static __device__ float g_part[(size_t)(3 * NCHB) * NB * NPOLAR * 3 * NLON];
static __device__ int   g_bjl [NLAT * 3];
static __device__ int   g_bcnt[NLAT * 3];

__device__ __forceinline__ int polar_map(int rl) { return rl < 20 ? rl : 701 + (rl - 20); }

// One-shot: exact support bounds per (l, dd in {0,1,2}, lq = l-1+dd).
// jl 4-aligned down, end 4-aligned up; padded taps hit exact zeros in K.
__global__ void init_bounds()
{
    int idx = blockIdx.x * blockDim.x + threadIdx.x;
    if (idx >= NLAT * 3) return;
    int l = idx / 3, dd = idx - 3 * l;
    int jl = 0, cnt = 0;
    int lq = l - 1 + dd;
    if (lq >= 1 && lq <= NLAT - 2) {
        if (l == 0 || l == NLAT - 1) { jl = -720; cnt = 1440; }
        else {
            double tp = l * DTH, tq = lq * DTH;
            double cph = (cos(2.0 * DTH) - cos(tp) * cos(tq)) / (sin(tp) * sin(tq));
            if (cph < 1.0) {
                int W = 720;
                if (cph > -1.0) W = (int)(acos(cph) / DTH) + 1;
                if (W >= 716) { jl = -720; cnt = 1440; }
                else { jl = -((W + 3) & ~3); int je = (W + 4) & ~3; cnt = je - jl; }
            }
        }
    }
    g_bjl[idx] = jl; g_bcnt[idx] = cnt;
}

struct Acc { float adu[4], adv[4], adh[4]; };

__device__ __forceinline__ void seg_loop(
    const float* __restrict__ kgc, const float* __restrict__ kgs,
    const float* __restrict__ kdc, const float* __restrict__ kds,
    const float* rh, const float* ru, const float* rv,
    int j0, int j1, int koff, Acc& a)
{
    if (j0 >= j1) return;
    float4 hA = *(const float4*)(rh + j0);
    float4 uA = *(const float4*)(ru + j0);
    float4 vA = *(const float4*)(rv + j0);
    for (int j = j0; j < j1; j += 4) {
        const float4 kc = *(const float4*)(kgc + koff + j);
        const float4 ks = *(const float4*)(kgs + koff + j);
        const float4 dc = *(const float4*)(kdc + koff + j);
        const float4 dz = *(const float4*)(kds + koff + j);
        float4 hB = *(const float4*)(rh + j + 4);
        float4 uB = *(const float4*)(ru + j + 4);
        float4 vB = *(const float4*)(rv + j + 4);
        float hb[8] = {hA.x,hA.y,hA.z,hA.w,hB.x,hB.y,hB.z,hB.w};
        float ub[8] = {uA.x,uA.y,uA.z,uA.w,uB.x,uB.y,uB.z,uB.w};
        float vb[8] = {vA.x,vA.y,vA.z,vA.w,vB.x,vB.y,vB.z,vB.w};
        float kcb[4] = {kc.x,kc.y,kc.z,kc.w};
        float ksb[4] = {ks.x,ks.y,ks.z,ks.w};
        float dcb[4] = {dc.x,dc.y,dc.z,dc.w};
        float dsb[4] = {dz.x,dz.y,dz.z,dz.w};
        #pragma unroll
        for (int jj = 0; jj < 4; ++jj)
            #pragma unroll
            for (int i = 0; i < 4; ++i) {
                a.adu[i] = fmaf(kcb[jj], hb[jj+i], a.adu[i]);
                a.adv[i] = fmaf(ksb[jj], hb[jj+i], a.adv[i]);
                a.adh[i] = fmaf(dcb[jj], ub[jj+i], a.adh[i]);
                a.adh[i] = fmaf(dsb[jj], vb[jj+i], a.adh[i]);
            }
        hA = hB; uA = uB; vA = vB;
    }
}

__device__ __forceinline__ void rk_epilogue(
    int stage, size_t idx, float kh, float ku, float kv,
    const float* __restrict__ h0, const float* __restrict__ uv0,
    float* __restrict__ outH, float* __restrict__ outUV)
{
    float y0h = h0[idx], y0u = uv0[2*idx], y0v = uv0[2*idx+1];
    if (stage == 4) {
        outH[idx] = y0h + (DT/6.f) * (g_acc[idx] + kh);
        float2 o;
        o.x = y0u + (DT/6.f) * (g_acc[FOFF + idx]   + ku);
        o.y = y0v + (DT/6.f) * (g_acc[2*FOFF + idx] + kv);
        reinterpret_cast<float2*>(outUV)[idx] = o;
    } else {
        if (stage == 1) {
            g_acc[idx] = kh; g_acc[FOFF+idx] = ku; g_acc[2*FOFF+idx] = kv;
        } else {
            g_acc[idx] += 2.f*kh; g_acc[FOFF+idx] += 2.f*ku; g_acc[2*FOFF+idx] += 2.f*kv;
        }
        float aa = (stage == 3) ? DT : 0.5f * DT;
        float* dst = (stage == 2) ? g_curB : g_curA;
        dst[idx] = y0h + aa*kh; dst[FOFF+idx] = y0u + aa*ku; dst[2*FOFF+idx] = y0v + aa*kv;
    }
}

#define SRC_SELECT()                                                          \
    const float *srcH, *srcU, *srcV; int us;                                  \
    if (stage == 1) { srcH = h0; srcU = uv0; srcV = uv0 + 1; us = 2; }        \
    else { const float* c_ = (stage == 3) ? g_curB : g_curA;                  \
           srcH = c_; srcU = c_ + FOFF; srcV = c_ + 2*FOFF; us = 1; }

// Vectorized gmem fetch of 4 consecutive field values starting at lon m
// (4-aligned, fully in [0, NLON-4]) for field f (0=h,1=u,2=v).
__device__ __forceinline__ float4 fetch4(
    const float* __restrict__ srcH, const float* __restrict__ uv0,
    const float* __restrict__ srcU, const float* __restrict__ srcV,
    int us, int f, size_t rowg, int m)
{
    if (us == 1) {
        const float* s = (f == 0) ? srcH : (f == 1 ? srcU : srcV);
        return *(const float4*)(s + rowg + m);
    }
    if (f == 0) return *(const float4*)(srcH + rowg + m);
    const float4 a = *(const float4*)(uv0 + 2 * (rowg + m));
    const float4 c = *(const float4*)(uv0 + 2 * (rowg + m) + 4);
    float4 x;
    if (f == 1) { x.x = a.x; x.y = a.z; x.z = c.x; x.w = c.z; }
    else        { x.x = a.y; x.y = a.w; x.z = c.y; x.w = c.w; }
    return x;
}

__device__ __forceinline__ float fetch1(
    const float* __restrict__ srcH,
    const float* __restrict__ srcU, const float* __restrict__ srcV,
    int us, int f, size_t rowg, int m)
{
    const float* s = (f == 0) ? srcH : (f == 1 ? srcU : srcV);
    return s[(rowg + m) * (f == 0 ? 1 : us)];
}

// ------------- interior lats: one block per (b, l, lon-tile) ---------------
__global__ void __launch_bounds__(BLK_A)
tendA_kernel(const float* __restrict__ h0, const float* __restrict__ uv0,
             const float* __restrict__ Kgc, const float* __restrict__ Kgs,
             const float* __restrict__ Kdc, const float* __restrict__ Kds,
             const float* __restrict__ fcor,
             float* __restrict__ outH, float* __restrict__ outUV, int stage)
{
    __shared__ __align__(16) float sh[9 * SMW_A];

    int tid = threadIdx.x, bx = blockIdx.x, b = blockIdx.y;
    int tile = bx & 1, li = bx >> 1;
    int l = (li & 1) ? (700 - (li >> 1)) : (LS + (li >> 1));  // heavy rows first
    int t0 = tile * TILE;

    SRC_SELECT();
    int base_m = t0 - HALO;                    // 4-aligned
    for (int e = tid; e < 9 * NF4_A; e += BLK_A) {
        int r = e / NF4_A;
        int q4 = (e - r * NF4_A) * 4;
        int f = r / 3, dd = r - f * 3;
        int lq = l - 1 + dd;
        size_t rowg = (size_t)(b * NLAT + lq) * NLON;
        int m = base_m + q4;
        float4 x;
        if (m >= 0 && m + 3 < NLON) {
            x = fetch4(srcH, uv0, srcU, srcV, us, f, rowg, m);
        } else {
            float t[4];
            #pragma unroll
            for (int i = 0; i < 4; ++i) {
                int mm = m + i;
                mm += (mm < 0) ? NLON : 0; mm -= (mm >= NLON) ? NLON : 0;
                t[i] = fetch1(srcH, srcU, srcV, us, f, rowg, mm);
            }
            x.x = t[0]; x.y = t[1]; x.z = t[2]; x.w = t[3];
        }
        *(float4*)(sh + r * SMW_A + q4) = x;
    }
    __syncthreads();
    if (tid >= COMP_A) return;

    Acc a;
    #pragma unroll
    for (int i = 0; i < 4; ++i) { a.adu[i]=0.f; a.adv[i]=0.f; a.adh[i]=0.f; }
    int n0 = tid * 4, off0 = HALO + n0;

    for (int dd = 0; dd < 3; ++dd) {
        int cnt = __ldg(&g_bcnt[l * 3 + dd]);
        if (cnt == 0) continue;
        int jl = __ldg(&g_bjl[l * 3 + dd]);
        int je = jl + cnt;
        jl = max(jl, -(HALO - 4)); je = min(je, HALO - 4);
        const float* rh = sh + (0*3 + dd) * SMW_A + off0;
        const float* ru = sh + (1*3 + dd) * SMW_A + off0;
        const float* rv = sh + (2*3 + dd) * SMW_A + off0;
        size_t ko = (size_t)(l * 5 + dd + 1) * NLON;
        seg_loop(Kgc+ko, Kgs+ko, Kdc+ko, Kds+ko, rh, ru, rv, jl, min(je, 0), NLON, a);
        seg_loop(Kgc+ko, Kgs+ko, Kdc+ko, Kds+ko, rh, ru, rv, max(jl, 0), je, 0, a);
    }

    float fl = __ldg(fcor + l);
    const float* cu = sh + (1*3 + 1) * SMW_A + off0;
    const float* cv = sh + (2*3 + 1) * SMW_A + off0;
    size_t rb = (size_t)(b * NLAT + l) * NLON + t0 + n0;
    #pragma unroll
    for (int i = 0; i < 4; ++i)
        rk_epilogue(stage, rb + i, -a.adh[i], -a.adu[i] - fl*cv[i],
                    -a.adv[i] + fl*cu[i], h0, uv0, outH, outUV);
}

// ------------- polar rows: per-(row, dd, j-chunk) partial sums --------------
__global__ void __launch_bounds__(BLK_B)
tendB_kernel(const float* __restrict__ h0, const float* __restrict__ uv0,
             const float* __restrict__ Kgc, const float* __restrict__ Kgs,
             const float* __restrict__ Kdc, const float* __restrict__ Kds,
             int stage)
{
    __shared__ __align__(16) float sh[3 * SMW_B];

    int tid = threadIdx.x, bx = blockIdx.x, b = blockIdx.y;
    int rl = bx / (3 * NCHB), rem = bx - rl * 3 * NCHB;
    int dd = rem / NCHB, c = rem - dd * NCHB;
    int l = polar_map(rl);

    int cnt = __ldg(&g_bcnt[l * 3 + dd]);
    if (cnt == 0) return;
    int jl = __ldg(&g_bjl[l * 3 + dd]);
    int steps = cnt >> 2;
    int per = (steps + NCHB - 1) / NCHB;
    int s0 = c * per, s1 = min(steps, s0 + per);
    if (s0 >= s1) return;
    int jA = jl + 4 * s0, jB = jl + 4 * s1;

    int lq = l - 1 + dd;
    SRC_SELECT();
    for (int e = tid; e < 3 * (NLON / 4); e += BLK_B) {
        int f = e / (NLON / 4);
        int m = (e - f * (NLON / 4)) * 4;
        size_t rowg = (size_t)(b * NLAT + lq) * NLON;
        float4 x = fetch4(srcH, uv0, srcU, srcV, us, f, rowg, m);
        int q = m + 720; if (q >= NLON) q -= NLON;
        float* dst = sh + f * SMW_B;
        *(float4*)(dst + q) = x;
        *(float4*)(dst + q + NLON) = x;
    }
    __syncthreads();
    if (tid >= 360) return;

    int n0 = tid * 4;
    Acc a;
    #pragma unroll
    for (int i = 0; i < 4; ++i) { a.adu[i]=0.f; a.adv[i]=0.f; a.adh[i]=0.f; }
    const float* rh = sh + 720 + n0;
    const float* ru = sh + SMW_B + 720 + n0;
    const float* rv = sh + 2*SMW_B + 720 + n0;
    size_t ko = (size_t)(l * 5 + dd + 1) * NLON;
    seg_loop(Kgc+ko, Kgs+ko, Kdc+ko, Kds+ko, rh, ru, rv, jA, min(jB,0), NLON, a);
    seg_loop(Kgc+ko, Kgs+ko, Kdc+ko, Kds+ko, rh, ru, rv, max(jA,0), jB, 0, a);

    int task = b * NPOLAR + rl;
    float* part = g_part + ((size_t)(dd * NCHB + c) * (NB * NPOLAR) + task) * (3 * NLON);
    *(float4*)(part + 0*NLON + n0) = *(float4*)a.adu;
    *(float4*)(part + 1*NLON + n0) = *(float4*)a.adv;
    *(float4*)(part + 2*NLON + n0) = *(float4*)a.adh;
}

// grid (NPOLAR, NB, 4): z splits longitude into 4 spans of 360, 1 lon/thread.
__global__ void __launch_bounds__(384)
reduceB_kernel(const float* __restrict__ h0, const float* __restrict__ uv0,
               const float* __restrict__ fcor,
               float* __restrict__ outH, float* __restrict__ outUV, int stage)
{
    int tid = threadIdx.x;
    if (tid >= 360) return;
    int rl = blockIdx.x, b = blockIdx.y;
    int lon = blockIdx.z * 360 + tid;
    int l = polar_map(rl);
    int task = b * NPOLAR + rl;

    float su = 0.f, sv = 0.f, sk = 0.f;
    for (int dd = 0; dd < 3; ++dd) {
        int cnt = __ldg(&g_bcnt[l * 3 + dd]);
        if (cnt == 0) continue;
        int steps = cnt >> 2;
        int per = (steps + NCHB - 1) / NCHB;
        int nact = (steps + per - 1) / per;
        for (int s = 0; s < nact; ++s) {
            const float* part = g_part +
                ((size_t)(dd * NCHB + s) * (NB * NPOLAR) + task) * (3 * NLON);
            su += __ldg(part + lon);
            sv += __ldg(part + NLON + lon);
            sk += __ldg(part + 2*NLON + lon);
        }
    }
    SRC_SELECT();
    float fl = __ldg(fcor + l);
    size_t g = (size_t)(b * NLAT + l) * NLON + lon;
    float uc = srcU[g*us], vc = srcV[g*us];
    rk_epilogue(stage, g, -sk, -su - fl*vc, -sv + fl*uc, h0, uv0, outH, outUV);
}

extern "C" void kernel_launch(void* const* d_in, const int* in_sizes, int n_in,
                              void* d_out, int out_size)
{
    const float* h0  = (const float*)d_in[0];
    const float* uv0 = (const float*)d_in[1];
    const float* Kgc = (const float*)d_in[2];
    const float* Kgs = (const float*)d_in[3];
    const float* Kdc = (const float*)d_in[4];
    const float* Kds = (const float*)d_in[5];
    const float* fc  = (const float*)d_in[6];
    float* outH  = (float*)d_out;
    float* outUV = (float*)d_out + FOFF;

    init_bounds<<<(NLAT * 3 + 127) / 128, 128>>>();

    for (int stage = 1; stage <= 4; ++stage) {
        tendB_kernel<<<dim3(NPOLAR * 3 * NCHB, NB), BLK_B>>>(h0, uv0, Kgc, Kgs, Kdc, Kds, stage);
        tendA_kernel<<<dim3(NINT * 2, NB), BLK_A>>>(h0, uv0, Kgc, Kgs, Kdc, Kds, fc, outH, outUV, stage);
        reduceB_kernel<<<dim3(NPOLAR, NB, 4), 384>>>(h0, uv0, fc, outH, outUV, stage);
    }
    (void)in_sizes; (void)n_in; (void)out_size;
}

// round 6
// speedup vs baseline: 8.9741x; 1.1436x over previous
#include <cuda_runtime.h>
#include <math.h>

#define NLAT 721
#define NLON 1440
#define NB   4
#define DT   0.01f
#define FOFF ((size_t)NB * NLAT * NLON)
#define DTH  (3.14159265358979323846 / 720.0)

#define LS     20
#define NPOLAR 40
#define NINT   (NLAT - NPOLAR)          // 681
#define NCHB   4
#define NPOLTASK (NPOLAR * 3 * NCHB)    // 480

#define HALO  32
#define SMW_A (NLON + 2 * HALO + 8)     // 1512
#define SMW_B 2896
#define SMEMSZ (9 * SMW_A * 4)          // 54432 B
#define BLK   384

static __device__ float g_curA[3 * FOFF];
static __device__ float g_curB[3 * FOFF];
static __device__ float g_acc [3 * FOFF];
static __device__ float g_part[(size_t)(3 * NCHB) * NB * NPOLAR * 3 * NLON];
static __device__ int   g_bjl [NLAT * 3];
static __device__ int   g_bcnt[NLAT * 3];

__device__ __forceinline__ int polar_map(int rl) { return rl < 20 ? rl : 701 + (rl - 20); }

__global__ void init_bounds()
{
    int idx = blockIdx.x * blockDim.x + threadIdx.x;
    if (idx >= NLAT * 3) return;
    int l = idx / 3, dd = idx - 3 * l;
    int jl = 0, cnt = 0;
    int lq = l - 1 + dd;
    if (lq >= 1 && lq <= NLAT - 2) {
        if (l == 0 || l == NLAT - 1) { jl = -720; cnt = 1440; }
        else {
            double tp = l * DTH, tq = lq * DTH;
            double cph = (cos(2.0 * DTH) - cos(tp) * cos(tq)) / (sin(tp) * sin(tq));
            if (cph < 1.0) {
                int W = 720;
                if (cph > -1.0) W = (int)(acos(cph) / DTH) + 1;
                if (W >= 716) { jl = -720; cnt = 1440; }
                else { jl = -((W + 3) & ~3); int je = (W + 4) & ~3; cnt = je - jl; }
            }
        }
    }
    g_bjl[idx] = jl; g_bcnt[idx] = cnt;
}

struct Acc { float adu[4], adv[4], adh[4]; };

__device__ __forceinline__ void seg_loop(
    const float* __restrict__ kgc, const float* __restrict__ kgs,
    const float* __restrict__ kdc, const float* __restrict__ kds,
    const float* rh, const float* ru, const float* rv,
    int j0, int j1, int koff, Acc& a)
{
    if (j0 >= j1) return;
    float4 hA = *(const float4*)(rh + j0);
    float4 uA = *(const float4*)(ru + j0);
    float4 vA = *(const float4*)(rv + j0);
    for (int j = j0; j < j1; j += 4) {
        const float4 kc = *(const float4*)(kgc + koff + j);
        const float4 ks = *(const float4*)(kgs + koff + j);
        const float4 dc = *(const float4*)(kdc + koff + j);
        const float4 dz = *(const float4*)(kds + koff + j);
        float4 hB = *(const float4*)(rh + j + 4);
        float4 uB = *(const float4*)(ru + j + 4);
        float4 vB = *(const float4*)(rv + j + 4);
        float hb[8] = {hA.x,hA.y,hA.z,hA.w,hB.x,hB.y,hB.z,hB.w};
        float ub[8] = {uA.x,uA.y,uA.z,uA.w,uB.x,uB.y,uB.z,uB.w};
        float vb[8] = {vA.x,vA.y,vA.z,vA.w,vB.x,vB.y,vB.z,vB.w};
        float kcb[4] = {kc.x,kc.y,kc.z,kc.w};
        float ksb[4] = {ks.x,ks.y,ks.z,ks.w};
        float dcb[4] = {dc.x,dc.y,dc.z,dc.w};
        float dsb[4] = {dz.x,dz.y,dz.z,dz.w};
        #pragma unroll
        for (int jj = 0; jj < 4; ++jj)
            #pragma unroll
            for (int i = 0; i < 4; ++i) {
                a.adu[i] = fmaf(kcb[jj], hb[jj+i], a.adu[i]);
                a.adv[i] = fmaf(ksb[jj], hb[jj+i], a.adv[i]);
                a.adh[i] = fmaf(dcb[jj], ub[jj+i], a.adh[i]);
                a.adh[i] = fmaf(dsb[jj], vb[jj+i], a.adh[i]);
            }
        hA = hB; uA = uB; vA = vB;
    }
}

// ---- templated source access (stage known at compile time) ----
template<int STAGE>
__device__ __forceinline__ float4 fetch4(const float* __restrict__ h0,
                                         const float* __restrict__ uv0,
                                         int f, size_t rowg, int m)
{
    if (STAGE == 1) {
        if (f == 0) return *(const float4*)(h0 + rowg + m);
        const float4 a = *(const float4*)(uv0 + 2 * (rowg + m));
        const float4 c = *(const float4*)(uv0 + 2 * (rowg + m) + 4);
        float4 x;
        if (f == 1) { x.x = a.x; x.y = a.z; x.z = c.x; x.w = c.z; }
        else        { x.x = a.y; x.y = a.w; x.z = c.y; x.w = c.w; }
        return x;
    } else {
        const float* c_ = (STAGE == 3) ? g_curB : g_curA;
        return *(const float4*)(c_ + (size_t)f * FOFF + rowg + m);
    }
}

template<int STAGE>
__device__ __forceinline__ float fetch1(const float* __restrict__ h0,
                                        const float* __restrict__ uv0,
                                        int f, size_t rowg, int m)
{
    if (STAGE == 1) {
        if (f == 0) return h0[rowg + m];
        return uv0[2 * (rowg + m) + (f - 1)];
    } else {
        const float* c_ = (STAGE == 3) ? g_curB : g_curA;
        return c_[(size_t)f * FOFF + rowg + m];
    }
}

template<int STAGE>
__device__ __forceinline__ void rk_epilogue(
    size_t idx, float kh, float ku, float kv,
    const float* __restrict__ h0, const float* __restrict__ uv0,
    float* __restrict__ outH, float* __restrict__ outUV)
{
    float y0h = h0[idx], y0u = uv0[2*idx], y0v = uv0[2*idx+1];
    if (STAGE == 4) {
        outH[idx] = y0h + (DT/6.f) * (g_acc[idx] + kh);
        float2 o;
        o.x = y0u + (DT/6.f) * (g_acc[FOFF + idx]   + ku);
        o.y = y0v + (DT/6.f) * (g_acc[2*FOFF + idx] + kv);
        reinterpret_cast<float2*>(outUV)[idx] = o;
    } else {
        if (STAGE == 1) {
            g_acc[idx] = kh; g_acc[FOFF+idx] = ku; g_acc[2*FOFF+idx] = kv;
        } else {
            g_acc[idx] += 2.f*kh; g_acc[FOFF+idx] += 2.f*ku; g_acc[2*FOFF+idx] += 2.f*kv;
        }
        const float aa = (STAGE == 3) ? DT : 0.5f * DT;
        float* dst = (STAGE == 2) ? g_curB : g_curA;
        dst[idx] = y0h + aa*kh; dst[FOFF+idx] = y0u + aa*ku; dst[2*FOFF+idx] = y0v + aa*kv;
    }
}

// ---- merged tendency kernel: polar chunks (bx < NPOLTASK) + interior rows ----
template<int STAGE>
__global__ void __launch_bounds__(BLK, 3)
tend_kernel(const float* __restrict__ h0, const float* __restrict__ uv0,
            const float* __restrict__ Kgc, const float* __restrict__ Kgs,
            const float* __restrict__ Kdc, const float* __restrict__ Kds,
            const float* __restrict__ fcor,
            float* __restrict__ outH, float* __restrict__ outUV)
{
    extern __shared__ __align__(16) float sh[];
    int tid = threadIdx.x, bx = blockIdx.x, b = blockIdx.y;

    if (bx < NPOLTASK) {
        // ---------------- polar chunk ----------------
        int rl = bx / (3 * NCHB), rem = bx - rl * 3 * NCHB;
        int dd = rem / NCHB, c = rem - dd * NCHB;
        int l = polar_map(rl);
        int cnt = __ldg(&g_bcnt[l * 3 + dd]);
        if (cnt == 0) return;
        int jl = __ldg(&g_bjl[l * 3 + dd]);
        int steps = cnt >> 2;
        int per = (steps + NCHB - 1) / NCHB;
        int s0 = c * per, s1 = min(steps, s0 + per);
        if (s0 >= s1) return;
        int jA = jl + 4 * s0, jB = jl + 4 * s1;

        int lq = l - 1 + dd;
        size_t rowg = (size_t)(b * NLAT + lq) * NLON;
        for (int e = tid; e < 3 * (NLON / 4); e += BLK) {
            int f = e / (NLON / 4);
            int m = (e - f * (NLON / 4)) * 4;
            float4 x = fetch4<STAGE>(h0, uv0, f, rowg, m);
            int q = m + 720; if (q >= NLON) q -= NLON;
            float* dst = sh + f * SMW_B;
            *(float4*)(dst + q) = x;
            *(float4*)(dst + q + NLON) = x;
        }
        __syncthreads();
        if (tid >= 360) return;

        int n0 = tid * 4;
        Acc a;
        #pragma unroll
        for (int i = 0; i < 4; ++i) { a.adu[i]=0.f; a.adv[i]=0.f; a.adh[i]=0.f; }
        const float* rh = sh + 720 + n0;
        const float* ru = sh + SMW_B + 720 + n0;
        const float* rv = sh + 2*SMW_B + 720 + n0;
        size_t ko = (size_t)(l * 5 + dd + 1) * NLON;
        seg_loop(Kgc+ko, Kgs+ko, Kdc+ko, Kds+ko, rh, ru, rv, jA, min(jB,0), NLON, a);
        seg_loop(Kgc+ko, Kgs+ko, Kdc+ko, Kds+ko, rh, ru, rv, max(jA,0), jB, 0, a);

        int task = b * NPOLAR + rl;
        float* part = g_part + ((size_t)(dd * NCHB + c) * (NB * NPOLAR) + task) * (3 * NLON);
        *(float4*)(part + 0*NLON + n0) = *(float4*)a.adu;
        *(float4*)(part + 1*NLON + n0) = *(float4*)a.adv;
        *(float4*)(part + 2*NLON + n0) = *(float4*)a.adh;
    } else {
        // ---------------- interior full row ----------------
        int li = bx - NPOLTASK;
        int l = (li & 1) ? (700 - (li >> 1)) : (LS + (li >> 1));

        for (int e = tid; e < 9 * (SMW_A / 4); e += BLK) {
            int r = e / (SMW_A / 4);
            int q4 = (e - r * (SMW_A / 4)) * 4;
            int f = r / 3, dd = r - f * 3;
            int lq = l - 1 + dd;
            size_t rowg = (size_t)(b * NLAT + lq) * NLON;
            int m = q4 - HALO;
            float4 x;
            if (m >= 0 && m + 3 < NLON) {
                x = fetch4<STAGE>(h0, uv0, f, rowg, m);
            } else {
                float t[4];
                #pragma unroll
                for (int i = 0; i < 4; ++i) {
                    int mm = m + i;
                    mm += (mm < 0) ? NLON : 0; mm -= (mm >= NLON) ? NLON : 0;
                    t[i] = fetch1<STAGE>(h0, uv0, f, rowg, mm);
                }
                x.x = t[0]; x.y = t[1]; x.z = t[2]; x.w = t[3];
            }
            *(float4*)(sh + r * SMW_A + q4) = x;
        }
        __syncthreads();
        if (tid >= 360) return;

        Acc a;
        #pragma unroll
        for (int i = 0; i < 4; ++i) { a.adu[i]=0.f; a.adv[i]=0.f; a.adh[i]=0.f; }
        int n0 = tid * 4, off0 = HALO + n0;

        for (int dd = 0; dd < 3; ++dd) {
            int cnt = __ldg(&g_bcnt[l * 3 + dd]);
            if (cnt == 0) continue;
            int jl = __ldg(&g_bjl[l * 3 + dd]);
            int je = jl + cnt;
            jl = max(jl, -HALO); je = min(je, HALO);
            const float* rh = sh + (0*3 + dd) * SMW_A + off0;
            const float* ru = sh + (1*3 + dd) * SMW_A + off0;
            const float* rv = sh + (2*3 + dd) * SMW_A + off0;
            size_t ko = (size_t)(l * 5 + dd + 1) * NLON;
            seg_loop(Kgc+ko, Kgs+ko, Kdc+ko, Kds+ko, rh, ru, rv, jl, min(je, 0), NLON, a);
            seg_loop(Kgc+ko, Kgs+ko, Kdc+ko, Kds+ko, rh, ru, rv, max(jl, 0), je, 0, a);
        }

        float fl = __ldg(fcor + l);
        const float* cu = sh + (1*3 + 1) * SMW_A + off0;
        const float* cv = sh + (2*3 + 1) * SMW_A + off0;
        size_t rb = (size_t)(b * NLAT + l) * NLON + n0;
        #pragma unroll
        for (int i = 0; i < 4; ++i)
            rk_epilogue<STAGE>(rb + i, -a.adh[i], -a.adu[i] - fl*cv[i],
                               -a.adv[i] + fl*cu[i], h0, uv0, outH, outUV);
    }
}

// grid (NPOLAR, NB, 4): z splits longitude into 4 spans of 360, 1 lon/thread.
template<int STAGE>
__global__ void __launch_bounds__(384)
reduceB_kernel(const float* __restrict__ h0, const float* __restrict__ uv0,
               const float* __restrict__ fcor,
               float* __restrict__ outH, float* __restrict__ outUV)
{
    int tid = threadIdx.x;
    if (tid >= 360) return;
    int rl = blockIdx.x, b = blockIdx.y;
    int lon = blockIdx.z * 360 + tid;
    int l = polar_map(rl);
    int task = b * NPOLAR + rl;

    float su = 0.f, sv = 0.f, sk = 0.f;
    for (int dd = 0; dd < 3; ++dd) {
        int cnt = __ldg(&g_bcnt[l * 3 + dd]);
        if (cnt == 0) continue;
        int steps = cnt >> 2;
        int per = (steps + NCHB - 1) / NCHB;
        int nact = (steps + per - 1) / per;
        for (int s = 0; s < nact; ++s) {
            const float* part = g_part +
                ((size_t)(dd * NCHB + s) * (NB * NPOLAR) + task) * (3 * NLON);
            su += __ldg(part + lon);
            sv += __ldg(part + NLON + lon);
            sk += __ldg(part + 2*NLON + lon);
        }
    }
    float fl = __ldg(fcor + l);
    size_t g = (size_t)(b * NLAT + l) * NLON + lon;
    float uc, vc;
    if (STAGE == 1) { uc = uv0[2*g]; vc = uv0[2*g+1]; }
    else {
        const float* c_ = (STAGE == 3) ? g_curB : g_curA;
        uc = c_[FOFF + g]; vc = c_[2*FOFF + g];
    }
    rk_epilogue<STAGE>(g, -sk, -su - fl*vc, -sv + fl*uc, h0, uv0, outH, outUV);
}

template<int STAGE>
static void run_stage(const float* h0, const float* uv0,
                      const float* Kgc, const float* Kgs,
                      const float* Kdc, const float* Kds, const float* fc,
                      float* outH, float* outUV)
{
    static bool attr_set = false;
    if (!attr_set) {
        cudaFuncSetAttribute(tend_kernel<1>, cudaFuncAttributeMaxDynamicSharedMemorySize, SMEMSZ);
        cudaFuncSetAttribute(tend_kernel<2>, cudaFuncAttributeMaxDynamicSharedMemorySize, SMEMSZ);
        cudaFuncSetAttribute(tend_kernel<3>, cudaFuncAttributeMaxDynamicSharedMemorySize, SMEMSZ);
        cudaFuncSetAttribute(tend_kernel<4>, cudaFuncAttributeMaxDynamicSharedMemorySize, SMEMSZ);
        attr_set = true;
    }
    tend_kernel<STAGE><<<dim3(NPOLTASK + NINT, NB), BLK, SMEMSZ>>>(
        h0, uv0, Kgc, Kgs, Kdc, Kds, fc, outH, outUV);
    reduceB_kernel<STAGE><<<dim3(NPOLAR, NB, 4), 384>>>(h0, uv0, fc, outH, outUV);
}

extern "C" void kernel_launch(void* const* d_in, const int* in_sizes, int n_in,
                              void* d_out, int out_size)
{
    const float* h0  = (const float*)d_in[0];
    const float* uv0 = (const float*)d_in[1];
    const float* Kgc = (const float*)d_in[2];
    const float* Kgs = (const float*)d_in[3];
    const float* Kdc = (const float*)d_in[4];
    const float* Kds = (const float*)d_in[5];
    const float* fc  = (const float*)d_in[6];
    float* outH  = (float*)d_out;
    float* outUV = (float*)d_out + FOFF;

    init_bounds<<<(NLAT * 3 + 127) / 128, 128>>>();

    run_stage<1>(h0, uv0, Kgc, Kgs, Kdc, Kds, fc, outH, outUV);
    run_stage<2>(h0, uv0, Kgc, Kgs, Kdc, Kds, fc, outH, outUV);
    run_stage<3>(h0, uv0, Kgc, Kgs, Kdc, Kds, fc, outH, outUV);
    run_stage<4>(h0, uv0, Kgc, Kgs, Kdc, Kds, fc, outH, outUV);

    (void)in_sizes; (void)n_in; (void)out_size;
}

// round 7
// speedup vs baseline: 9.9586x; 1.1097x over previous
#include <cuda_runtime.h>
#include <math.h>

#define NLAT 721
#define NLON 1440
#define NB   4
#define DT   0.01f
#define FOFF ((size_t)NB * NLAT * NLON)
#define DTH  (3.14159265358979323846 / 720.0)

#define LS     20
#define NPOLAR 40
#define NINT   (NLAT - NPOLAR)          // 681
#define NCHB   4
#define NPOLTASK (NPOLAR * 3 * NCHB)    // 480

#define HALO  32
#define KW_A  (2 * HALO)                // 64 floats per staged K row (interior)
#define SMW_A (NLON + 2 * HALO + 8)     // 1512
#define SMW_B 2896
#define KW_B  368                       // max polar chunk taps (360) + pad
// interior: 9 field rows + 12 K rows; polar: 3 field rows + 4 K rows
#define SMEMSZ ((9 * SMW_A + 12 * KW_A) * 4)   // 57504 B (>= polar need 40640 B)
#define BLK   384

static __device__ float g_curA[3 * FOFF];
static __device__ float g_curB[3 * FOFF];
static __device__ float g_acc [3 * FOFF];
static __device__ float g_part[(size_t)(3 * NCHB) * NB * NPOLAR * 3 * NLON];
static __device__ int   g_bjl [NLAT * 3];
static __device__ int   g_bcnt[NLAT * 3];

__device__ __forceinline__ int polar_map(int rl) { return rl < 20 ? rl : 701 + (rl - 20); }

__global__ void init_bounds()
{
    int idx = blockIdx.x * blockDim.x + threadIdx.x;
    if (idx >= NLAT * 3) return;
    int l = idx / 3, dd = idx - 3 * l;
    int jl = 0, cnt = 0;
    int lq = l - 1 + dd;
    if (lq >= 1 && lq <= NLAT - 2) {
        if (l == 0 || l == NLAT - 1) { jl = -720; cnt = 1440; }
        else {
            double tp = l * DTH, tq = lq * DTH;
            double cph = (cos(2.0 * DTH) - cos(tp) * cos(tq)) / (sin(tp) * sin(tq));
            if (cph < 1.0) {
                int W = 720;
                if (cph > -1.0) W = (int)(acos(cph) / DTH) + 1;
                if (W >= 716) { jl = -720; cnt = 1440; }
                else { jl = -((W + 3) & ~3); int je = (W + 4) & ~3; cnt = je - jl; }
            }
        }
    }
    g_bjl[idx] = jl; g_bcnt[idx] = cnt;
}

struct Acc { float adu[4], adv[4], adh[4]; };

// Correlation over j in [j0, j1), 4-aligned, all pointers into SMEM.
// K pointers pre-offset so tap weight = k*[j]; field rows pre-offset so
// element = r*[j] .. r*[j+7] window.
__device__ __forceinline__ void seg_loop(
    const float* kgc, const float* kgs, const float* kdc, const float* kds,
    const float* rh, const float* ru, const float* rv,
    int j0, int j1, Acc& a)
{
    if (j0 >= j1) return;
    float4 hA = *(const float4*)(rh + j0);
    float4 uA = *(const float4*)(ru + j0);
    float4 vA = *(const float4*)(rv + j0);
    for (int j = j0; j < j1; j += 4) {
        const float4 kc = *(const float4*)(kgc + j);
        const float4 ks = *(const float4*)(kgs + j);
        const float4 dc = *(const float4*)(kdc + j);
        const float4 dz = *(const float4*)(kds + j);
        float4 hB = *(const float4*)(rh + j + 4);
        float4 uB = *(const float4*)(ru + j + 4);
        float4 vB = *(const float4*)(rv + j + 4);
        float hb[8] = {hA.x,hA.y,hA.z,hA.w,hB.x,hB.y,hB.z,hB.w};
        float ub[8] = {uA.x,uA.y,uA.z,uA.w,uB.x,uB.y,uB.z,uB.w};
        float vb[8] = {vA.x,vA.y,vA.z,vA.w,vB.x,vB.y,vB.z,vB.w};
        float kcb[4] = {kc.x,kc.y,kc.z,kc.w};
        float ksb[4] = {ks.x,ks.y,ks.z,ks.w};
        float dcb[4] = {dc.x,dc.y,dc.z,dc.w};
        float dsb[4] = {dz.x,dz.y,dz.z,dz.w};
        #pragma unroll
        for (int jj = 0; jj < 4; ++jj)
            #pragma unroll
            for (int i = 0; i < 4; ++i) {
                a.adu[i] = fmaf(kcb[jj], hb[jj+i], a.adu[i]);
                a.adv[i] = fmaf(ksb[jj], hb[jj+i], a.adv[i]);
                a.adh[i] = fmaf(dcb[jj], ub[jj+i], a.adh[i]);
                a.adh[i] = fmaf(dsb[jj], vb[jj+i], a.adh[i]);
            }
        hA = hB; uA = uB; vA = vB;
    }
}

template<int STAGE>
__device__ __forceinline__ float4 fetch4(const float* __restrict__ h0,
                                         const float* __restrict__ uv0,
                                         int f, size_t rowg, int m)
{
    if (STAGE == 1) {
        if (f == 0) return *(const float4*)(h0 + rowg + m);
        const float4 a = *(const float4*)(uv0 + 2 * (rowg + m));
        const float4 c = *(const float4*)(uv0 + 2 * (rowg + m) + 4);
        float4 x;
        if (f == 1) { x.x = a.x; x.y = a.z; x.z = c.x; x.w = c.z; }
        else        { x.x = a.y; x.y = a.w; x.z = c.y; x.w = c.w; }
        return x;
    } else {
        const float* c_ = (STAGE == 3) ? g_curB : g_curA;
        return *(const float4*)(c_ + (size_t)f * FOFF + rowg + m);
    }
}

template<int STAGE>
__device__ __forceinline__ float fetch1(const float* __restrict__ h0,
                                        const float* __restrict__ uv0,
                                        int f, size_t rowg, int m)
{
    if (STAGE == 1) {
        if (f == 0) return h0[rowg + m];
        return uv0[2 * (rowg + m) + (f - 1)];
    } else {
        const float* c_ = (STAGE == 3) ? g_curB : g_curA;
        return c_[(size_t)f * FOFF + rowg + m];
    }
}

template<int STAGE>
__device__ __forceinline__ void rk_epilogue(
    size_t idx, float kh, float ku, float kv,
    const float* __restrict__ h0, const float* __restrict__ uv0,
    float* __restrict__ outH, float* __restrict__ outUV)
{
    float y0h = h0[idx], y0u = uv0[2*idx], y0v = uv0[2*idx+1];
    if (STAGE == 4) {
        outH[idx] = y0h + (DT/6.f) * (g_acc[idx] + kh);
        float2 o;
        o.x = y0u + (DT/6.f) * (g_acc[FOFF + idx]   + ku);
        o.y = y0v + (DT/6.f) * (g_acc[2*FOFF + idx] + kv);
        reinterpret_cast<float2*>(outUV)[idx] = o;
    } else {
        if (STAGE == 1) {
            g_acc[idx] = kh; g_acc[FOFF+idx] = ku; g_acc[2*FOFF+idx] = kv;
        } else {
            g_acc[idx] += 2.f*kh; g_acc[FOFF+idx] += 2.f*ku; g_acc[2*FOFF+idx] += 2.f*kv;
        }
        const float aa = (STAGE == 3) ? DT : 0.5f * DT;
        float* dst = (STAGE == 2) ? g_curB : g_curA;
        dst[idx] = y0h + aa*kh; dst[FOFF+idx] = y0u + aa*ku; dst[2*FOFF+idx] = y0v + aa*kv;
    }
}

template<int STAGE>
__global__ void __launch_bounds__(BLK, 3)
tend_kernel(const float* __restrict__ h0, const float* __restrict__ uv0,
            const float* __restrict__ Kgc, const float* __restrict__ Kgs,
            const float* __restrict__ Kdc, const float* __restrict__ Kds,
            const float* __restrict__ fcor,
            float* __restrict__ outH, float* __restrict__ outUV)
{
    extern __shared__ __align__(16) float sh[];
    int tid = threadIdx.x, bx = blockIdx.x, b = blockIdx.y;
    const float* Ks[4] = {Kgc, Kgs, Kdc, Kds};

    if (bx < NPOLTASK) {
        // ---------------- polar chunk ----------------
        int rl = bx / (3 * NCHB), rem = bx - rl * 3 * NCHB;
        int dd = rem / NCHB, c = rem - dd * NCHB;
        int l = polar_map(rl);
        int cnt = __ldg(&g_bcnt[l * 3 + dd]);
        if (cnt == 0) return;
        int jl = __ldg(&g_bjl[l * 3 + dd]);
        int steps = cnt >> 2;
        int per = (steps + NCHB - 1) / NCHB;
        int s0 = c * per, s1 = min(steps, s0 + per);
        if (s0 >= s1) return;
        int jA = jl + 4 * s0, jB = jl + 4 * s1;
        int ntap = jB - jA;                       // <= 360

        int lq = l - 1 + dd;
        size_t rowg = (size_t)(b * NLAT + lq) * NLON;
        float* shF = sh;                          // 3 x SMW_B
        float* shK = sh + 3 * SMW_B;              // 4 x KW_B

        for (int e = tid; e < 3 * (NLON / 4); e += BLK) {
            int f = e / (NLON / 4);
            int m = (e - f * (NLON / 4)) * 4;
            float4 x = fetch4<STAGE>(h0, uv0, f, rowg, m);
            int q = m + 720; if (q >= NLON) q -= NLON;
            float* dst = shF + f * SMW_B;
            *(float4*)(dst + q) = x;
            *(float4*)(dst + q + NLON) = x;
        }
        // stage the chunk's K taps (4 kernels, taps jA..jB, linear by t=j-jA)
        {
            size_t ko = (size_t)(l * 5 + dd + 1) * NLON;
            int ng = ntap >> 2;                    // float4 groups per kernel
            for (int e = tid; e < 4 * ng; e += BLK) {
                int k = e / ng;
                int t4 = (e - k * ng) * 4;
                int j = jA + t4;                   // 4-aligned; group same sign
                int gm = (j < 0) ? (NLON + j) : j;
                *(float4*)(shK + k * KW_B + t4) = *(const float4*)(Ks[k] + ko + gm);
            }
        }
        __syncthreads();
        if (tid >= 360) return;

        int n0 = tid * 4;
        Acc a;
        #pragma unroll
        for (int i = 0; i < 4; ++i) { a.adu[i]=0.f; a.adv[i]=0.f; a.adh[i]=0.f; }
        seg_loop(shK + 0*KW_B - jA, shK + 1*KW_B - jA,
                 shK + 2*KW_B - jA, shK + 3*KW_B - jA,
                 shF + 720 + n0, shF + SMW_B + 720 + n0, shF + 2*SMW_B + 720 + n0,
                 jA, jB, a);

        int task = b * NPOLAR + rl;
        float* part = g_part + ((size_t)(dd * NCHB + c) * (NB * NPOLAR) + task) * (3 * NLON);
        *(float4*)(part + 0*NLON + n0) = *(float4*)a.adu;
        *(float4*)(part + 1*NLON + n0) = *(float4*)a.adv;
        *(float4*)(part + 2*NLON + n0) = *(float4*)a.adh;
    } else {
        // ---------------- interior full row ----------------
        int li = bx - NPOLTASK;
        int l = (li & 1) ? (700 - (li >> 1)) : (LS + (li >> 1));
        float* shF = sh;                          // 9 x SMW_A
        float* shK = sh + 9 * SMW_A;              // 12 x KW_A, centered at +HALO

        for (int e = tid; e < 9 * (SMW_A / 4); e += BLK) {
            int r = e / (SMW_A / 4);
            int q4 = (e - r * (SMW_A / 4)) * 4;
            int f = r / 3, dd = r - f * 3;
            int lq = l - 1 + dd;
            size_t rowg = (size_t)(b * NLAT + lq) * NLON;
            int m = q4 - HALO;
            float4 x;
            if (m >= 0 && m + 3 < NLON) {
                x = fetch4<STAGE>(h0, uv0, f, rowg, m);
            } else {
                float t[4];
                #pragma unroll
                for (int i = 0; i < 4; ++i) {
                    int mm = m + i;
                    mm += (mm < 0) ? NLON : 0; mm -= (mm >= NLON) ? NLON : 0;
                    t[i] = fetch1<STAGE>(h0, uv0, f, rowg, mm);
                }
                x.x = t[0]; x.y = t[1]; x.z = t[2]; x.w = t[3];
            }
            *(float4*)(shF + r * SMW_A + q4) = x;
        }
        // stage 12 K rows, centered window j in [-HALO, HALO)
        for (int e = tid; e < 12 * (KW_A / 4); e += BLK) {
            int r = e / (KW_A / 4);
            int q4 = (e - r * (KW_A / 4)) * 4;
            int dd = r / 4, k = r - dd * 4;
            int j = q4 - HALO;                    // group fully <0 or >=0
            int gm = (j < 0) ? (NLON + j) : j;
            size_t ko = (size_t)(l * 5 + dd + 1) * NLON;
            *(float4*)(shK + r * KW_A + q4) = *(const float4*)(Ks[k] + ko + gm);
        }
        __syncthreads();
        if (tid >= 360) return;

        Acc a;
        #pragma unroll
        for (int i = 0; i < 4; ++i) { a.adu[i]=0.f; a.adv[i]=0.f; a.adh[i]=0.f; }
        int n0 = tid * 4, off0 = HALO + n0;

        for (int dd = 0; dd < 3; ++dd) {
            int cnt = __ldg(&g_bcnt[l * 3 + dd]);
            if (cnt == 0) continue;
            int jl = __ldg(&g_bjl[l * 3 + dd]);
            int je = jl + cnt;
            jl = max(jl, -HALO); je = min(je, HALO);
            const float* kb = shK + dd * 4 * KW_A + HALO;
            seg_loop(kb, kb + KW_A, kb + 2*KW_A, kb + 3*KW_A,
                     shF + (0*3 + dd) * SMW_A + off0,
                     shF + (1*3 + dd) * SMW_A + off0,
                     shF + (2*3 + dd) * SMW_A + off0,
                     jl, je, a);
        }

        float fl = __ldg(fcor + l);
        const float* cu = shF + (1*3 + 1) * SMW_A + off0;
        const float* cv = shF + (2*3 + 1) * SMW_A + off0;
        size_t rb = (size_t)(b * NLAT + l) * NLON + n0;
        #pragma unroll
        for (int i = 0; i < 4; ++i)
            rk_epilogue<STAGE>(rb + i, -a.adh[i], -a.adu[i] - fl*cv[i],
                               -a.adv[i] + fl*cu[i], h0, uv0, outH, outUV);
    }
}

template<int STAGE>
__global__ void __launch_bounds__(384)
reduceB_kernel(const float* __restrict__ h0, const float* __restrict__ uv0,
               const float* __restrict__ fcor,
               float* __restrict__ outH, float* __restrict__ outUV)
{
    int tid = threadIdx.x;
    if (tid >= 360) return;
    int rl = blockIdx.x, b = blockIdx.y;
    int lon = blockIdx.z * 360 + tid;
    int l = polar_map(rl);
    int task = b * NPOLAR + rl;

    float su = 0.f, sv = 0.f, sk = 0.f;
    for (int dd = 0; dd < 3; ++dd) {
        int cnt = __ldg(&g_bcnt[l * 3 + dd]);
        if (cnt == 0) continue;
        int steps = cnt >> 2;
        int per = (steps + NCHB - 1) / NCHB;
        int nact = (steps + per - 1) / per;
        for (int s = 0; s < nact; ++s) {
            const float* part = g_part +
                ((size_t)(dd * NCHB + s) * (NB * NPOLAR) + task) * (3 * NLON);
            su += __ldg(part + lon);
            sv += __ldg(part + NLON + lon);
            sk += __ldg(part + 2*NLON + lon);
        }
    }
    float fl = __ldg(fcor + l);
    size_t g = (size_t)(b * NLAT + l) * NLON + lon;
    float uc, vc;
    if (STAGE == 1) { uc = uv0[2*g]; vc = uv0[2*g+1]; }
    else {
        const float* c_ = (STAGE == 3) ? g_curB : g_curA;
        uc = c_[FOFF + g]; vc = c_[2*FOFF + g];
    }
    rk_epilogue<STAGE>(g, -sk, -su - fl*vc, -sv + fl*uc, h0, uv0, outH, outUV);
}

template<int STAGE>
static void run_stage(const float* h0, const float* uv0,
                      const float* Kgc, const float* Kgs,
                      const float* Kdc, const float* Kds, const float* fc,
                      float* outH, float* outUV)
{
    tend_kernel<STAGE><<<dim3(NPOLTASK + NINT, NB), BLK, SMEMSZ>>>(
        h0, uv0, Kgc, Kgs, Kdc, Kds, fc, outH, outUV);
    reduceB_kernel<STAGE><<<dim3(NPOLAR, NB, 4), 384>>>(h0, uv0, fc, outH, outUV);
}

extern "C" void kernel_launch(void* const* d_in, const int* in_sizes, int n_in,
                              void* d_out, int out_size)
{
    const float* h0  = (const float*)d_in[0];
    const float* uv0 = (const float*)d_in[1];
    const float* Kgc = (const float*)d_in[2];
    const float* Kgs = (const float*)d_in[3];
    const float* Kdc = (const float*)d_in[4];
    const float* Kds = (const float*)d_in[5];
    const float* fc  = (const float*)d_in[6];
    float* outH  = (float*)d_out;
    float* outUV = (float*)d_out + FOFF;

    static bool attr_set = false;
    if (!attr_set) {
        cudaFuncSetAttribute(tend_kernel<1>, cudaFuncAttributeMaxDynamicSharedMemorySize, SMEMSZ);
        cudaFuncSetAttribute(tend_kernel<2>, cudaFuncAttributeMaxDynamicSharedMemorySize, SMEMSZ);
        cudaFuncSetAttribute(tend_kernel<3>, cudaFuncAttributeMaxDynamicSharedMemorySize, SMEMSZ);
        cudaFuncSetAttribute(tend_kernel<4>, cudaFuncAttributeMaxDynamicSharedMemorySize, SMEMSZ);
        attr_set = true;
    }

    init_bounds<<<(NLAT * 3 + 127) / 128, 128>>>();

    run_stage<1>(h0, uv0, Kgc, Kgs, Kdc, Kds, fc, outH, outUV);
    run_stage<2>(h0, uv0, Kgc, Kgs, Kdc, Kds, fc, outH, outUV);
    run_stage<3>(h0, uv0, Kgc, Kgs, Kdc, Kds, fc, outH, outUV);
    run_stage<4>(h0, uv0, Kgc, Kgs, Kdc, Kds, fc, outH, outUV);

    (void)in_sizes; (void)n_in; (void)out_size;
}